// round 1
// baseline (speedup 1.0000x reference)
#include <cuda_runtime.h>
#include <math.h>

#define B_SZ   2
#define T_SEQ  1024
#define BT     2048       // B*T
#define DMODEL 4096
#define NH     32
#define NKVH   8
#define HDIM   128

// ---------------- scratch (no allocations allowed) ----------------
__device__ float g_q[BT * 4096];
__device__ float g_k[BT * 1024];
__device__ float g_v[BT * 1024];
__device__ float g_attn[BT * 4096];

// ---------------- SGEMM: C[M,N] = A[M,K] @ B[K,N], row-major ------
// 128x128 tile, BK=16, 256 threads, 8x8 per-thread microtile.
__global__ __launch_bounds__(256) void sgemm_kernel(
    const float* __restrict__ A, const float* __restrict__ B,
    float* __restrict__ C, int M, int N, int K)
{
    __shared__ float As[16][128];   // transposed A tile
    __shared__ float Bs[16][128];

    const int tid = threadIdx.x;
    const int tx = tid & 15;        // 0..15 -> 8 cols each
    const int ty = tid >> 4;        // 0..15 -> 8 rows each
    const int m0 = blockIdx.y * 128;
    const int n0 = blockIdx.x * 128;

    const int aRow  = tid >> 2;     // 0..63
    const int aCol4 = tid & 3;      // float4 index in 16-wide k
    const int bRow  = tid >> 5;     // 0..7
    const int bCol4 = tid & 31;     // float4 index in 128-wide n

    float acc[8][8];
    #pragma unroll
    for (int i = 0; i < 8; i++)
        #pragma unroll
        for (int j = 0; j < 8; j++) acc[i][j] = 0.f;

    for (int k0 = 0; k0 < K; k0 += 16) {
        #pragma unroll
        for (int i = 0; i < 2; i++) {
            int r = aRow + i * 64;
            float4 av = *(const float4*)&A[(m0 + r) * K + k0 + aCol4 * 4];
            As[aCol4 * 4 + 0][r] = av.x;
            As[aCol4 * 4 + 1][r] = av.y;
            As[aCol4 * 4 + 2][r] = av.z;
            As[aCol4 * 4 + 3][r] = av.w;
        }
        #pragma unroll
        for (int i = 0; i < 2; i++) {
            int r = bRow + i * 8;
            *(float4*)&Bs[r][bCol4 * 4] =
                *(const float4*)&B[(k0 + r) * N + n0 + bCol4 * 4];
        }
        __syncthreads();

        #pragma unroll
        for (int k = 0; k < 16; k++) {
            float ra[8], rb[8];
            *(float4*)&ra[0] = *(float4*)&As[k][ty * 8];
            *(float4*)&ra[4] = *(float4*)&As[k][ty * 8 + 4];
            *(float4*)&rb[0] = *(float4*)&Bs[k][tx * 8];
            *(float4*)&rb[4] = *(float4*)&Bs[k][tx * 8 + 4];
            #pragma unroll
            for (int i = 0; i < 8; i++)
                #pragma unroll
                for (int j = 0; j < 8; j++)
                    acc[i][j] += ra[i] * rb[j];
        }
        __syncthreads();
    }

    #pragma unroll
    for (int i = 0; i < 8; i++) {
        int row = m0 + ty * 8 + i;
        #pragma unroll
        for (int j4 = 0; j4 < 2; j4++) {
            float4 v;
            v.x = acc[i][j4 * 4 + 0];
            v.y = acc[i][j4 * 4 + 1];
            v.z = acc[i][j4 * 4 + 2];
            v.w = acc[i][j4 * 4 + 3];
            *(float4*)&C[row * N + n0 + tx * 8 + j4 * 4] = v;
        }
    }
}

// ---------------- RoPE (exact reference semantics) ----------------
// out[2i]   = x[2i]  *cos(a(2i))   - x[2i+1]*sin(a(2i))
// out[2i+1] = x[2i+1]*cos(a(2i+1)) + x[2i]  *sin(a(2i+1))
// a(j) = t * 10000^(-(j mod 64)/64), j = dim index within head (HD=128)
__global__ void rope_kernel(float* __restrict__ data, int cols, int total_pairs,
                            const int* __restrict__ sp)
{
    int idx = blockIdx.x * blockDim.x + threadIdx.x;
    if (idx >= total_pairs) return;
    int halfcols = cols >> 1;
    int row = idx / halfcols;
    int p   = idx - row * halfcols;
    int c0  = p * 2;
    int j0  = c0 & (HDIM - 1);
    int start = (sp == nullptr) ? 0 : *sp;
    float t = (float)(start + (row & (T_SEQ - 1)));

    const float lf = 9.210340371976184f;           // ln(10000)
    float a0 = t * expf(-(float)(j0 & 63)       * (lf / 64.f));
    float a1 = t * expf(-(float)((j0 + 1) & 63) * (lf / 64.f));
    float c0v, s0v, c1v, s1v;
    sincosf(a0, &s0v, &c0v);
    sincosf(a1, &s1v, &c1v);

    float* base = data + (size_t)row * cols + c0;
    float x0 = base[0], x1 = base[1];
    base[0] = x0 * c0v - x1 * s0v;
    base[1] = x1 * c1v + x0 * s1v;
}

// ---------------- Flash attention (causal, GQA) -------------------
// grid: (T/64, NH, B), 256 threads.
// thread = (row r = tid>>2 of 64, quarter q4 = tid&3 owning 32 of HD).
// K/V tiles of 32 rows in smem, layout [kk][quarter][33] -> conflict-free.
__global__ __launch_bounds__(256) void attn_kernel(
    const float* __restrict__ Q, const float* __restrict__ K,
    const float* __restrict__ V, float* __restrict__ O)
{
    __shared__ float Ks[32 * 132];
    __shared__ float Vs[32 * 132];

    const int b  = blockIdx.z;
    const int h  = blockIdx.y;
    const int m0 = blockIdx.x * 64;
    const int kvh = h >> 2;                        // GROUP = 4
    const int tid = threadIdx.x;
    const int q4 = tid & 3;
    const int r  = tid >> 2;
    const int qpos = m0 + r;
    const float scale = 0.08838834764831845f;      // 1/sqrt(128)

    float qreg[32];
    {
        const float* qp = Q + (size_t)(b * T_SEQ + qpos) * 4096 + h * HDIM + q4 * 32;
        #pragma unroll
        for (int i = 0; i < 8; i++) {
            float4 v = *(const float4*)(qp + i * 4);
            qreg[i * 4 + 0] = v.x * scale;
            qreg[i * 4 + 1] = v.y * scale;
            qreg[i * 4 + 2] = v.z * scale;
            qreg[i * 4 + 3] = v.w * scale;
        }
    }

    float m_i = -INFINITY, l_i = 0.f;
    float acc[32];
    #pragma unroll
    for (int d = 0; d < 32; d++) acc[d] = 0.f;

    const int ktiles = m0 / 32 + 2;                // cover [0, m0+64)
    for (int it = 0; it < ktiles; it++) {
        const int kt = it * 32;
        // cooperative K/V tile load (32 rows x 128 cols), padded layout
        #pragma unroll
        for (int i = 0; i < 4; i++) {
            int idx4 = tid + i * 256;
            int kk = idx4 >> 5;
            int c4 = idx4 & 31;
            int gofs = (b * T_SEQ + kt + kk) * 1024 + kvh * HDIM + c4 * 4;
            float4 kv4 = *(const float4*)&K[gofs];
            float4 vv4 = *(const float4*)&V[gofs];
            int sofs = kk * 132 + (c4 >> 3) * 33 + (c4 & 7) * 4;
            Ks[sofs + 0] = kv4.x; Ks[sofs + 1] = kv4.y;
            Ks[sofs + 2] = kv4.z; Ks[sofs + 3] = kv4.w;
            Vs[sofs + 0] = vv4.x; Vs[sofs + 1] = vv4.y;
            Vs[sofs + 2] = vv4.z; Vs[sofs + 3] = vv4.w;
        }
        __syncthreads();

        float s[32];
        #pragma unroll
        for (int kk = 0; kk < 32; kk++) {
            const float* kp = &Ks[kk * 132 + q4 * 33];
            float s0 = 0.f, s1 = 0.f, s2 = 0.f, s3 = 0.f;
            #pragma unroll
            for (int d = 0; d < 32; d += 4) {
                s0 += qreg[d + 0] * kp[d + 0];
                s1 += qreg[d + 1] * kp[d + 1];
                s2 += qreg[d + 2] * kp[d + 2];
                s3 += qreg[d + 3] * kp[d + 3];
            }
            float sum = (s0 + s1) + (s2 + s3);
            sum += __shfl_xor_sync(0xFFFFFFFFu, sum, 1);
            sum += __shfl_xor_sync(0xFFFFFFFFu, sum, 2);
            s[kk] = (kt + kk <= qpos) ? sum : -INFINITY;
        }

        float mnew = m_i;
        #pragma unroll
        for (int kk = 0; kk < 32; kk++) mnew = fmaxf(mnew, s[kk]);
        float corr = __expf(m_i - mnew);           // -inf -> 0 on first tile
        float psum = 0.f;
        #pragma unroll
        for (int kk = 0; kk < 32; kk++) {
            s[kk] = __expf(s[kk] - mnew);
            psum += s[kk];
        }
        l_i = l_i * corr + psum;
        m_i = mnew;
        #pragma unroll
        for (int d = 0; d < 32; d++) acc[d] *= corr;

        #pragma unroll
        for (int kk = 0; kk < 32; kk++) {
            const float* vp = &Vs[kk * 132 + q4 * 33];
            float pv = s[kk];
            #pragma unroll
            for (int d = 0; d < 32; d++) acc[d] += pv * vp[d];
        }
        __syncthreads();
    }

    float inv = 1.0f / l_i;
    float* op = O + (size_t)(b * T_SEQ + qpos) * 4096 + h * HDIM + q4 * 32;
    #pragma unroll
    for (int i = 0; i < 8; i++) {
        float4 v;
        v.x = acc[i * 4 + 0] * inv;
        v.y = acc[i * 4 + 1] * inv;
        v.z = acc[i * 4 + 2] * inv;
        v.w = acc[i * 4 + 3] * inv;
        *(float4*)(op + i * 4) = v;
    }
}

// ---------------- launcher ----------------------------------------
extern "C" void kernel_launch(void* const* d_in, const int* in_sizes, int n_in,
                              void* d_out, int out_size)
{
    const float* x  = (const float*)d_in[0];
    const float* wq = (const float*)d_in[1];
    const float* wk = (const float*)d_in[2];
    const float* wv = (const float*)d_in[3];
    const float* wo = (const float*)d_in[4];
    const int*   sp = (n_in > 5) ? (const int*)d_in[5] : nullptr;
    float* out = (float*)d_out;
    (void)in_sizes; (void)out_size;

    float *gq, *gk, *gv, *ga;
    cudaGetSymbolAddress((void**)&gq, g_q);
    cudaGetSymbolAddress((void**)&gk, g_k);
    cudaGetSymbolAddress((void**)&gv, g_v);
    cudaGetSymbolAddress((void**)&ga, g_attn);

    // QKV projections
    sgemm_kernel<<<dim3(32, 16), 256>>>(x, wq, gq, BT, 4096, 4096);
    sgemm_kernel<<<dim3(8, 16), 256>>>(x, wk, gk, BT, 1024, 4096);
    sgemm_kernel<<<dim3(8, 16), 256>>>(x, wv, gv, BT, 1024, 4096);

    // RoPE on q and k
    rope_kernel<<<(BT * 2048) / 256, 256>>>(gq, 4096, BT * 2048, sp);
    rope_kernel<<<(BT * 512) / 256, 256>>>(gk, 1024, BT * 512, sp);

    // causal GQA flash attention
    attn_kernel<<<dim3(T_SEQ / 64, NH, B_SZ), 256>>>(gq, gk, gv, ga);

    // output projection
    sgemm_kernel<<<dim3(32, 16), 256>>>(ga, wo, out, BT, 4096, 4096);
}

// round 3
// speedup vs baseline: 2.0454x; 2.0454x over previous
#include <cuda_runtime.h>
#include <cuda_bf16.h>
#include <math.h>
#include <stdint.h>

#define B_SZ   2
#define T_SEQ  1024
#define BT     2048
#define NH     32
#define HDIM   128

// ================= scratch =================
__device__ float g_q[BT * 4096];
__device__ float g_k[BT * 1024];
__device__ float g_v[BT * 1024];
__device__ float g_attn[BT * 4096];
__device__ __nv_bfloat16 g_xh[BT * 4096], g_xl[BT * 4096];
__device__ __nv_bfloat16 g_ah[BT * 4096], g_al[BT * 4096];
__device__ __nv_bfloat16 g_wqh[4096 * 4096], g_wql[4096 * 4096];
__device__ __nv_bfloat16 g_wkh[4096 * 1024], g_wkl[4096 * 1024];
__device__ __nv_bfloat16 g_wvh[4096 * 1024], g_wvl[4096 * 1024];
__device__ __nv_bfloat16 g_woh[4096 * 4096], g_wol[4096 * 4096];

// ================= helpers =================
__device__ __forceinline__ uint32_t smem_u32(const void* p) {
    uint32_t a;
    asm("{ .reg .u64 t; cvta.to.shared.u64 t, %1; cvt.u32.u64 %0, t; }"
        : "=r"(a) : "l"(p));
    return a;
}
// swizzled byte offset inside a 128(rows)x32(k) bf16 tile:
// two 64B k-rows packed per 128B physical row; 16B unit xor-swizzled.
__device__ __forceinline__ uint32_t swz(uint32_t r, uint32_t u) {
    return ((r >> 1) << 7) | (((((r & 1) << 2) | u) ^ ((r >> 1) & 7)) << 4);
}

#define CP_ASYNC16(dst, src) \
    asm volatile("cp.async.cg.shared.global [%0], [%1], 16;" :: "r"(dst), "l"(src))
#define CP_COMMIT() asm volatile("cp.async.commit_group;" ::: "memory")
#define CP_WAIT1()  asm volatile("cp.async.wait_group 1;" ::: "memory")

#define LDSM4(r0, r1, r2, r3, a) \
    asm volatile("ldmatrix.sync.aligned.m8n8.x4.shared.b16 {%0,%1,%2,%3}, [%4];" \
        : "=r"(r0), "=r"(r1), "=r"(r2), "=r"(r3) : "r"(a))

#define MMA16816(c, a0, a1, a2, a3, b0, b1) \
    asm volatile("mma.sync.aligned.m16n8k16.row.col.f32.bf16.bf16.f32 " \
        "{%0,%1,%2,%3}, {%4,%5,%6,%7}, {%8,%9}, {%0,%1,%2,%3};" \
        : "+f"((c)[0]), "+f"((c)[1]), "+f"((c)[2]), "+f"((c)[3]) \
        : "r"(a0), "r"(a1), "r"(a2), "r"(a3), "r"(b0), "r"(b1))

// ============ split fp32 -> bf16 hi/lo (row-major) ============
__global__ void split_kernel(const float* __restrict__ in,
                             __nv_bfloat16* __restrict__ hi,
                             __nv_bfloat16* __restrict__ lo, int n4)
{
    int i = blockIdx.x * blockDim.x + threadIdx.x;
    if (i >= n4) return;
    float4 v = ((const float4*)in)[i];
    __nv_bfloat16 h0 = __float2bfloat16(v.x);
    __nv_bfloat16 h1 = __float2bfloat16(v.y);
    __nv_bfloat16 h2 = __float2bfloat16(v.z);
    __nv_bfloat16 h3 = __float2bfloat16(v.w);
    __nv_bfloat162* hp = (__nv_bfloat162*)hi;
    __nv_bfloat162* lp = (__nv_bfloat162*)lo;
    hp[2 * i]     = __nv_bfloat162(h0, h1);
    hp[2 * i + 1] = __nv_bfloat162(h2, h3);
    lp[2 * i]     = __nv_bfloat162(__float2bfloat16(v.x - __bfloat162float(h0)),
                                   __float2bfloat16(v.y - __bfloat162float(h1)));
    lp[2 * i + 1] = __nv_bfloat162(__float2bfloat16(v.z - __bfloat162float(h2)),
                                   __float2bfloat16(v.w - __bfloat162float(h3)));
}

// ============ transpose + split: W[K][N] fp32 -> Wt[N][K] bf16 hi/lo ============
__global__ __launch_bounds__(256) void tsplit_kernel(
    const float* __restrict__ W, __nv_bfloat16* __restrict__ hi,
    __nv_bfloat16* __restrict__ lo, int K, int N)
{
    __shared__ float s[32][33];
    const int n0 = blockIdx.x * 32, k0 = blockIdx.y * 32;
    const int c = threadIdx.x & 31, r0 = threadIdx.x >> 5;
    #pragma unroll
    for (int rr = 0; rr < 4; rr++) {
        int r = r0 + rr * 8;
        s[r][c] = W[(size_t)(k0 + r) * N + n0 + c];
    }
    __syncthreads();
    #pragma unroll
    for (int rr = 0; rr < 4; rr++) {
        int r = r0 + rr * 8;
        float v = s[c][r];
        __nv_bfloat16 h = __float2bfloat16(v);
        size_t o = (size_t)(n0 + r) * K + k0 + c;
        hi[o] = h;
        lo[o] = __float2bfloat16(v - __bfloat162float(h));
    }
}

// ============ bf16x3 GEMM via mma.sync: C[M,N] = A[M,K] @ Bt[N,K]^T ============
// 128x128 tile, K-chunk 32, 3-stage cp.async pipeline, 8 warps (2m x 4n).
#define KC      32
#define NSTAGE  3
#define TILE_B  8192              // 128x32 bf16
#define STAGE_B (4 * TILE_B)      // Ah, Al, Bh, Bl
#define GEMM_SMEM (NSTAGE * STAGE_B)

__global__ __launch_bounds__(256, 1) void gemm3_kernel(
    const __nv_bfloat16* __restrict__ Ah, const __nv_bfloat16* __restrict__ Al,
    const __nv_bfloat16* __restrict__ Bh, const __nv_bfloat16* __restrict__ Bl,
    float* __restrict__ C, int M, int N, int K)
{
    extern __shared__ char smem[];
    const uint32_t sb = smem_u32(smem);
    const int tid = threadIdx.x, wid = tid >> 5, lid = tid & 31;
    const int m0 = blockIdx.y * 128, n0 = blockIdx.x * 128;
    const int warp_m = wid & 1, warp_n = wid >> 1;
    const int NCH = K / KC;

    // precomputed ldmatrix relative offsets (within a stage)
    uint32_t rel_a[4][2], rel_b[2][2];
    {
        uint32_t ar = (uint32_t)(warp_m * 64 + (lid & 15));
        uint32_t au = (uint32_t)(lid >> 4);
        #pragma unroll
        for (int mi = 0; mi < 4; mi++)
            #pragma unroll
            for (int k16 = 0; k16 < 2; k16++)
                rel_a[mi][k16] = swz(ar + mi * 16, au + k16 * 2);
        uint32_t br = (uint32_t)(warp_n * 32 + (lid & 7) + ((lid >> 4) << 3));
        uint32_t bu = (uint32_t)((lid >> 3) & 1);
        #pragma unroll
        for (int ng = 0; ng < 2; ng++)
            #pragma unroll
            for (int k16 = 0; k16 < 2; k16++)
                rel_b[ng][k16] = swz(br + ng * 16, bu + k16 * 2);
    }

    float acc[4][4][4];
    #pragma unroll
    for (int mi = 0; mi < 4; mi++)
        #pragma unroll
        for (int ni = 0; ni < 4; ni++)
            #pragma unroll
            for (int j = 0; j < 4; j++) acc[mi][ni][j] = 0.f;

    // producer: 8 cp.async units of 16B per thread per stage
    auto load_stage = [&](int s, int chunk) {
        const int k0 = chunk * KC;
        const uint32_t st = sb + s * STAGE_B;
        #pragma unroll
        for (int t = 0; t < 8; t++) {
            int g = t * 256 + tid;
            int tile = g >> 9;
            int w = g & 511;
            int r = w >> 2, u = w & 3;
            uint32_t dst = st + tile * TILE_B + swz(r, u);
            const __nv_bfloat16* src;
            if (tile == 0)      src = Ah + (size_t)(m0 + r) * K + k0 + u * 8;
            else if (tile == 1) src = Al + (size_t)(m0 + r) * K + k0 + u * 8;
            else if (tile == 2) src = Bh + (size_t)(n0 + r) * K + k0 + u * 8;
            else                src = Bl + (size_t)(n0 + r) * K + k0 + u * 8;
            CP_ASYNC16(dst, src);
        }
    };

    load_stage(0, 0); CP_COMMIT();
    load_stage(1, 1); CP_COMMIT();

    for (int i = 0; i < NCH; i++) {
        CP_WAIT1();
        __syncthreads();
        int nxt = i + NSTAGE - 1;
        if (nxt < NCH) load_stage(nxt % NSTAGE, nxt);
        CP_COMMIT();

        const uint32_t st = sb + (i % NSTAGE) * STAGE_B;
        const uint32_t ah_b = st, al_b = st + TILE_B;
        const uint32_t bh_b = st + 2 * TILE_B, bl_b = st + 3 * TILE_B;

        #pragma unroll
        for (int k16 = 0; k16 < 2; k16++) {
            uint32_t afh[4][4], afl[4][4], bfh[2][4], bfl[2][4];
            #pragma unroll
            for (int mi = 0; mi < 4; mi++) {
                LDSM4(afh[mi][0], afh[mi][1], afh[mi][2], afh[mi][3], ah_b + rel_a[mi][k16]);
                LDSM4(afl[mi][0], afl[mi][1], afl[mi][2], afl[mi][3], al_b + rel_a[mi][k16]);
            }
            #pragma unroll
            for (int ng = 0; ng < 2; ng++) {
                LDSM4(bfh[ng][0], bfh[ng][1], bfh[ng][2], bfh[ng][3], bh_b + rel_b[ng][k16]);
                LDSM4(bfl[ng][0], bfl[ng][1], bfl[ng][2], bfl[ng][3], bl_b + rel_b[ng][k16]);
            }
            #pragma unroll
            for (int mi = 0; mi < 4; mi++)
                #pragma unroll
                for (int ni = 0; ni < 4; ni++) {
                    int ng = ni >> 1, rp = (ni & 1) * 2;
                    MMA16816(acc[mi][ni], afh[mi][0], afh[mi][1], afh[mi][2], afh[mi][3],
                             bfh[ng][rp], bfh[ng][rp + 1]);
                    MMA16816(acc[mi][ni], afh[mi][0], afh[mi][1], afh[mi][2], afh[mi][3],
                             bfl[ng][rp], bfl[ng][rp + 1]);
                    MMA16816(acc[mi][ni], afl[mi][0], afl[mi][1], afl[mi][2], afl[mi][3],
                             bfh[ng][rp], bfh[ng][rp + 1]);
                }
        }
    }

    // epilogue: c-frag layout -> fp32 C
    #pragma unroll
    for (int mi = 0; mi < 4; mi++) {
        int row = m0 + warp_m * 64 + mi * 16 + (lid >> 2);
        #pragma unroll
        for (int ni = 0; ni < 4; ni++) {
            int col = n0 + warp_n * 32 + ni * 8 + (lid & 3) * 2;
            float2 v0 = make_float2(acc[mi][ni][0], acc[mi][ni][1]);
            float2 v1 = make_float2(acc[mi][ni][2], acc[mi][ni][3]);
            *(float2*)&C[(size_t)row * N + col] = v0;
            *(float2*)&C[(size_t)(row + 8) * N + col] = v1;
        }
    }
}

// ================= RoPE (exact reference semantics) =================
__global__ void rope_kernel(float* __restrict__ data, int cols, int total_pairs,
                            const int* __restrict__ sp)
{
    int idx = blockIdx.x * blockDim.x + threadIdx.x;
    if (idx >= total_pairs) return;
    int halfcols = cols >> 1;
    int row = idx / halfcols;
    int p   = idx - row * halfcols;
    int c0  = p * 2;
    int j0  = c0 & (HDIM - 1);
    int start = (sp == nullptr) ? 0 : *sp;
    float t = (float)(start + (row & (T_SEQ - 1)));
    const float lf = 9.210340371976184f;
    float a0 = t * expf(-(float)(j0 & 63)       * (lf / 64.f));
    float a1 = t * expf(-(float)((j0 + 1) & 63) * (lf / 64.f));
    float c0v, s0v, c1v, s1v;
    sincosf(a0, &s0v, &c0v);
    sincosf(a1, &s1v, &c1v);
    float* base = data + (size_t)row * cols + c0;
    float x0 = base[0], x1 = base[1];
    base[0] = x0 * c0v - x1 * s0v;
    base[1] = x1 * c1v + x0 * s1v;
}

// ================= Flash attention (causal, GQA), fp32 =================
__global__ __launch_bounds__(256) void attn_kernel(
    const float* __restrict__ Q, const float* __restrict__ K,
    const float* __restrict__ V, float* __restrict__ O)
{
    __shared__ float Ks[32 * 132];
    __shared__ float Vs[32 * 132];
    const int b  = blockIdx.z;
    const int h  = blockIdx.y;
    const int m0 = blockIdx.x * 64;
    const int kvh = h >> 2;
    const int tid = threadIdx.x;
    const int q4 = tid & 3;
    const int r  = tid >> 2;
    const int qpos = m0 + r;
    const float scale = 0.08838834764831845f;

    float qreg[32];
    {
        const float* qp = Q + (size_t)(b * T_SEQ + qpos) * 4096 + h * HDIM + q4 * 32;
        #pragma unroll
        for (int i = 0; i < 8; i++) {
            float4 v = *(const float4*)(qp + i * 4);
            qreg[i * 4 + 0] = v.x * scale; qreg[i * 4 + 1] = v.y * scale;
            qreg[i * 4 + 2] = v.z * scale; qreg[i * 4 + 3] = v.w * scale;
        }
    }
    float m_i = -INFINITY, l_i = 0.f;
    float acc[32];
    #pragma unroll
    for (int d = 0; d < 32; d++) acc[d] = 0.f;

    const int ktiles = m0 / 32 + 2;
    for (int it = 0; it < ktiles; it++) {
        const int kt = it * 32;
        #pragma unroll
        for (int i = 0; i < 4; i++) {
            int idx4 = tid + i * 256;
            int kk = idx4 >> 5, c4 = idx4 & 31;
            int gofs = (b * T_SEQ + kt + kk) * 1024 + kvh * HDIM + c4 * 4;
            float4 kv4 = *(const float4*)&K[gofs];
            float4 vv4 = *(const float4*)&V[gofs];
            int sofs = kk * 132 + (c4 >> 3) * 33 + (c4 & 7) * 4;
            Ks[sofs + 0] = kv4.x; Ks[sofs + 1] = kv4.y;
            Ks[sofs + 2] = kv4.z; Ks[sofs + 3] = kv4.w;
            Vs[sofs + 0] = vv4.x; Vs[sofs + 1] = vv4.y;
            Vs[sofs + 2] = vv4.z; Vs[sofs + 3] = vv4.w;
        }
        __syncthreads();

        float s[32];
        #pragma unroll
        for (int kk = 0; kk < 32; kk++) {
            const float* kp = &Ks[kk * 132 + q4 * 33];
            float s0 = 0.f, s1 = 0.f, s2 = 0.f, s3 = 0.f;
            #pragma unroll
            for (int d = 0; d < 32; d += 4) {
                s0 += qreg[d + 0] * kp[d + 0];
                s1 += qreg[d + 1] * kp[d + 1];
                s2 += qreg[d + 2] * kp[d + 2];
                s3 += qreg[d + 3] * kp[d + 3];
            }
            float sum = (s0 + s1) + (s2 + s3);
            sum += __shfl_xor_sync(0xFFFFFFFFu, sum, 1);
            sum += __shfl_xor_sync(0xFFFFFFFFu, sum, 2);
            s[kk] = (kt + kk <= qpos) ? sum : -INFINITY;
        }
        float mnew = m_i;
        #pragma unroll
        for (int kk = 0; kk < 32; kk++) mnew = fmaxf(mnew, s[kk]);
        float corr = __expf(m_i - mnew);
        float psum = 0.f;
        #pragma unroll
        for (int kk = 0; kk < 32; kk++) { s[kk] = __expf(s[kk] - mnew); psum += s[kk]; }
        l_i = l_i * corr + psum;
        m_i = mnew;
        #pragma unroll
        for (int d = 0; d < 32; d++) acc[d] *= corr;
        #pragma unroll
        for (int kk = 0; kk < 32; kk++) {
            const float* vp = &Vs[kk * 132 + q4 * 33];
            float pv = s[kk];
            #pragma unroll
            for (int d = 0; d < 32; d++) acc[d] += pv * vp[d];
        }
        __syncthreads();
    }
    float inv = 1.0f / l_i;
    float* op = O + (size_t)(b * T_SEQ + qpos) * 4096 + h * HDIM + q4 * 32;
    #pragma unroll
    for (int i = 0; i < 8; i++) {
        float4 v;
        v.x = acc[i * 4 + 0] * inv; v.y = acc[i * 4 + 1] * inv;
        v.z = acc[i * 4 + 2] * inv; v.w = acc[i * 4 + 3] * inv;
        *(float4*)(op + i * 4) = v;
    }
}

// ================= launcher =================
extern "C" void kernel_launch(void* const* d_in, const int* in_sizes, int n_in,
                              void* d_out, int out_size)
{
    const float* x  = (const float*)d_in[0];
    const float* wq = (const float*)d_in[1];
    const float* wk = (const float*)d_in[2];
    const float* wv = (const float*)d_in[3];
    const float* wo = (const float*)d_in[4];
    const int*   sp = (n_in > 5) ? (const int*)d_in[5] : nullptr;
    float* out = (float*)d_out;
    (void)in_sizes; (void)out_size;

    float *gq, *gk, *gv, *ga;
    cudaGetSymbolAddress((void**)&gq, g_q);
    cudaGetSymbolAddress((void**)&gk, g_k);
    cudaGetSymbolAddress((void**)&gv, g_v);
    cudaGetSymbolAddress((void**)&ga, g_attn);
    __nv_bfloat16 *xh, *xl, *ah, *al, *wqh, *wql, *wkh, *wkl, *wvh, *wvl, *woh, *wol;
    cudaGetSymbolAddress((void**)&xh, g_xh);   cudaGetSymbolAddress((void**)&xl, g_xl);
    cudaGetSymbolAddress((void**)&ah, g_ah);   cudaGetSymbolAddress((void**)&al, g_al);
    cudaGetSymbolAddress((void**)&wqh, g_wqh); cudaGetSymbolAddress((void**)&wql, g_wql);
    cudaGetSymbolAddress((void**)&wkh, g_wkh); cudaGetSymbolAddress((void**)&wkl, g_wkl);
    cudaGetSymbolAddress((void**)&wvh, g_wvh); cudaGetSymbolAddress((void**)&wvl, g_wvl);
    cudaGetSymbolAddress((void**)&woh, g_woh); cudaGetSymbolAddress((void**)&wol, g_wol);

    cudaFuncSetAttribute(gemm3_kernel, cudaFuncAttributeMaxDynamicSharedMemorySize, GEMM_SMEM);

    // split x; transpose-split weights
    int n4x = BT * 4096 / 4;
    split_kernel<<<n4x / 256, 256>>>(x, xh, xl, n4x);
    tsplit_kernel<<<dim3(4096 / 32, 4096 / 32), 256>>>(wq, wqh, wql, 4096, 4096);
    tsplit_kernel<<<dim3(1024 / 32, 4096 / 32), 256>>>(wk, wkh, wkl, 4096, 1024);
    tsplit_kernel<<<dim3(1024 / 32, 4096 / 32), 256>>>(wv, wvh, wvl, 4096, 1024);
    tsplit_kernel<<<dim3(4096 / 32, 4096 / 32), 256>>>(wo, woh, wol, 4096, 4096);

    // projections on tensor cores (mma.sync bf16x3)
    gemm3_kernel<<<dim3(4096 / 128, BT / 128), 256, GEMM_SMEM>>>(xh, xl, wqh, wql, gq, BT, 4096, 4096);
    gemm3_kernel<<<dim3(1024 / 128, BT / 128), 256, GEMM_SMEM>>>(xh, xl, wkh, wkl, gk, BT, 1024, 4096);
    gemm3_kernel<<<dim3(1024 / 128, BT / 128), 256, GEMM_SMEM>>>(xh, xl, wvh, wvl, gv, BT, 1024, 4096);

    // RoPE
    rope_kernel<<<(BT * 2048) / 256, 256>>>(gq, 4096, BT * 2048, sp);
    rope_kernel<<<(BT * 512) / 256, 256>>>(gk, 1024, BT * 512, sp);

    // attention
    attn_kernel<<<dim3(T_SEQ / 64, NH, B_SZ), 256>>>(gq, gk, gv, ga);

    // output projection
    split_kernel<<<n4x / 256, 256>>>(ga, ah, al, n4x);
    gemm3_kernel<<<dim3(4096 / 128, BT / 128), 256, GEMM_SMEM>>>(ah, al, woh, wol, out, BT, 4096, 4096);
}

// round 4
// speedup vs baseline: 2.1227x; 1.0378x over previous
#include <cuda_runtime.h>
#include <cuda_bf16.h>
#include <math.h>
#include <stdint.h>

#define B_SZ   2
#define T_SEQ  1024
#define BT     2048
#define NH     32
#define HDIM   128

// ================= scratch =================
__device__ float g_q[BT * 4096];
__device__ float g_k[BT * 1024];
__device__ float g_v[BT * 1024];
__device__ float g_attn[BT * 4096];
__device__ __nv_bfloat16 g_xh[BT * 4096], g_xl[BT * 4096];
__device__ __nv_bfloat16 g_ah[BT * 4096], g_al[BT * 4096];
__device__ __nv_bfloat16 g_wqh[4096 * 4096], g_wql[4096 * 4096];
__device__ __nv_bfloat16 g_wkh[4096 * 1024], g_wkl[4096 * 1024];
__device__ __nv_bfloat16 g_wvh[4096 * 1024], g_wvl[4096 * 1024];
__device__ __nv_bfloat16 g_woh[4096 * 4096], g_wol[4096 * 4096];

// ================= helpers =================
__device__ __forceinline__ uint32_t smem_u32(const void* p) {
    uint32_t a;
    asm("{ .reg .u64 t; cvta.to.shared.u64 t, %1; cvt.u32.u64 %0, t; }"
        : "=r"(a) : "l"(p));
    return a;
}
// swizzled byte offset in a (rows)x32(k) bf16 tile: two 64B k-rows per 128B
// physical row; 16B unit xor-swizzled.
__device__ __forceinline__ uint32_t swz(uint32_t r, uint32_t u) {
    return ((r >> 1) << 7) | (((((r & 1) << 2) | u) ^ ((r >> 1) & 7)) << 4);
}

#define CP_ASYNC16(dst, src) \
    asm volatile("cp.async.cg.shared.global [%0], [%1], 16;" :: "r"(dst), "l"(src))
#define CP_COMMIT() asm volatile("cp.async.commit_group;" ::: "memory")
#define CP_WAIT1()  asm volatile("cp.async.wait_group 1;" ::: "memory")
#define CP_WAIT2()  asm volatile("cp.async.wait_group 2;" ::: "memory")

#define LDSM4(r0, r1, r2, r3, a) \
    asm volatile("ldmatrix.sync.aligned.m8n8.x4.shared.b16 {%0,%1,%2,%3}, [%4];" \
        : "=r"(r0), "=r"(r1), "=r"(r2), "=r"(r3) : "r"(a))

#define MMA16816(c, a0, a1, a2, a3, b0, b1) \
    asm volatile("mma.sync.aligned.m16n8k16.row.col.f32.bf16.bf16.f32 " \
        "{%0,%1,%2,%3}, {%4,%5,%6,%7}, {%8,%9}, {%0,%1,%2,%3};" \
        : "+f"((c)[0]), "+f"((c)[1]), "+f"((c)[2]), "+f"((c)[3]) \
        : "r"(a0), "r"(a1), "r"(a2), "r"(a3), "r"(b0), "r"(b1))

// ============ split fp32 -> bf16 hi/lo (row-major) ============
__global__ void split_kernel(const float* __restrict__ in,
                             __nv_bfloat16* __restrict__ hi,
                             __nv_bfloat16* __restrict__ lo, int n4)
{
    int i = blockIdx.x * blockDim.x + threadIdx.x;
    if (i >= n4) return;
    float4 v = ((const float4*)in)[i];
    __nv_bfloat16 h0 = __float2bfloat16(v.x);
    __nv_bfloat16 h1 = __float2bfloat16(v.y);
    __nv_bfloat16 h2 = __float2bfloat16(v.z);
    __nv_bfloat16 h3 = __float2bfloat16(v.w);
    __nv_bfloat162* hp = (__nv_bfloat162*)hi;
    __nv_bfloat162* lp = (__nv_bfloat162*)lo;
    hp[2 * i]     = __nv_bfloat162(h0, h1);
    hp[2 * i + 1] = __nv_bfloat162(h2, h3);
    lp[2 * i]     = __nv_bfloat162(__float2bfloat16(v.x - __bfloat162float(h0)),
                                   __float2bfloat16(v.y - __bfloat162float(h1)));
    lp[2 * i + 1] = __nv_bfloat162(__float2bfloat16(v.z - __bfloat162float(h2)),
                                   __float2bfloat16(v.w - __bfloat162float(h3)));
}

// ============ transpose + split: W[K][N] fp32 -> Wt[N][K] bf16 hi/lo ============
__global__ __launch_bounds__(256) void tsplit_kernel(
    const float* __restrict__ W, __nv_bfloat16* __restrict__ hi,
    __nv_bfloat16* __restrict__ lo, int K, int N)
{
    __shared__ float s[32][33];
    const int n0 = blockIdx.x * 32, k0 = blockIdx.y * 32;
    const int c = threadIdx.x & 31, r0 = threadIdx.x >> 5;
    #pragma unroll
    for (int rr = 0; rr < 4; rr++) {
        int r = r0 + rr * 8;
        s[r][c] = W[(size_t)(k0 + r) * N + n0 + c];
    }
    __syncthreads();
    #pragma unroll
    for (int rr = 0; rr < 4; rr++) {
        int r = r0 + rr * 8;
        float v = s[c][r];
        __nv_bfloat16 h = __float2bfloat16(v);
        size_t o = (size_t)(n0 + r) * K + k0 + c;
        hi[o] = h;
        lo[o] = __float2bfloat16(v - __bfloat162float(h));
    }
}

// ============ bf16x3 GEMM 128x128 (for K/V): C = A @ Bt^T ============
#define KC      32
#define NSTAGE  3
#define TILE_B  8192
#define STAGE_B (4 * TILE_B)
#define GEMM_SMEM (NSTAGE * STAGE_B)

__global__ __launch_bounds__(256, 1) void gemm3_kernel(
    const __nv_bfloat16* __restrict__ Ah, const __nv_bfloat16* __restrict__ Al,
    const __nv_bfloat16* __restrict__ Bh, const __nv_bfloat16* __restrict__ Bl,
    float* __restrict__ C, int M, int N, int K)
{
    extern __shared__ char smem[];
    const uint32_t sb = smem_u32(smem);
    const int tid = threadIdx.x, wid = tid >> 5, lid = tid & 31;
    const int m0 = blockIdx.y * 128, n0 = blockIdx.x * 128;
    const int warp_m = wid & 1, warp_n = wid >> 1;
    const int NCH = K / KC;

    uint32_t rel_a[4][2], rel_b[2][2];
    {
        uint32_t ar = (uint32_t)(warp_m * 64 + (lid & 15));
        uint32_t au = (uint32_t)(lid >> 4);
        #pragma unroll
        for (int mi = 0; mi < 4; mi++)
            #pragma unroll
            for (int k16 = 0; k16 < 2; k16++)
                rel_a[mi][k16] = swz(ar + mi * 16, au + k16 * 2);
        uint32_t br = (uint32_t)(warp_n * 32 + (lid & 7) + ((lid >> 4) << 3));
        uint32_t bu = (uint32_t)((lid >> 3) & 1);
        #pragma unroll
        for (int ng = 0; ng < 2; ng++)
            #pragma unroll
            for (int k16 = 0; k16 < 2; k16++)
                rel_b[ng][k16] = swz(br + ng * 16, bu + k16 * 2);
    }

    float acc[4][4][4];
    #pragma unroll
    for (int mi = 0; mi < 4; mi++)
        #pragma unroll
        for (int ni = 0; ni < 4; ni++)
            #pragma unroll
            for (int j = 0; j < 4; j++) acc[mi][ni][j] = 0.f;

    auto load_stage = [&](int s, int chunk) {
        const int k0 = chunk * KC;
        const uint32_t st = sb + s * STAGE_B;
        #pragma unroll
        for (int t = 0; t < 8; t++) {
            int g = t * 256 + tid;
            int tile = g >> 9;
            int w = g & 511;
            int r = w >> 2, u = w & 3;
            uint32_t dst = st + tile * TILE_B + swz(r, u);
            const __nv_bfloat16* src;
            if (tile == 0)      src = Ah + (size_t)(m0 + r) * K + k0 + u * 8;
            else if (tile == 1) src = Al + (size_t)(m0 + r) * K + k0 + u * 8;
            else if (tile == 2) src = Bh + (size_t)(n0 + r) * K + k0 + u * 8;
            else                src = Bl + (size_t)(n0 + r) * K + k0 + u * 8;
            CP_ASYNC16(dst, src);
        }
    };

    load_stage(0, 0); CP_COMMIT();
    load_stage(1, 1); CP_COMMIT();

    for (int i = 0; i < NCH; i++) {
        CP_WAIT1();
        __syncthreads();
        int nxt = i + NSTAGE - 1;
        if (nxt < NCH) load_stage(nxt % NSTAGE, nxt);
        CP_COMMIT();

        const uint32_t st = sb + (i % NSTAGE) * STAGE_B;
        const uint32_t ah_b = st, al_b = st + TILE_B;
        const uint32_t bh_b = st + 2 * TILE_B, bl_b = st + 3 * TILE_B;

        #pragma unroll
        for (int k16 = 0; k16 < 2; k16++) {
            uint32_t afh[4][4], afl[4][4], bfh[2][4], bfl[2][4];
            #pragma unroll
            for (int mi = 0; mi < 4; mi++) {
                LDSM4(afh[mi][0], afh[mi][1], afh[mi][2], afh[mi][3], ah_b + rel_a[mi][k16]);
                LDSM4(afl[mi][0], afl[mi][1], afl[mi][2], afl[mi][3], al_b + rel_a[mi][k16]);
            }
            #pragma unroll
            for (int ng = 0; ng < 2; ng++) {
                LDSM4(bfh[ng][0], bfh[ng][1], bfh[ng][2], bfh[ng][3], bh_b + rel_b[ng][k16]);
                LDSM4(bfl[ng][0], bfl[ng][1], bfl[ng][2], bfl[ng][3], bl_b + rel_b[ng][k16]);
            }
            #pragma unroll
            for (int mi = 0; mi < 4; mi++)
                #pragma unroll
                for (int ni = 0; ni < 4; ni++) {
                    int ng = ni >> 1, rp = (ni & 1) * 2;
                    MMA16816(acc[mi][ni], afh[mi][0], afh[mi][1], afh[mi][2], afh[mi][3],
                             bfh[ng][rp], bfh[ng][rp + 1]);
                    MMA16816(acc[mi][ni], afh[mi][0], afh[mi][1], afh[mi][2], afh[mi][3],
                             bfl[ng][rp], bfl[ng][rp + 1]);
                    MMA16816(acc[mi][ni], afl[mi][0], afl[mi][1], afl[mi][2], afl[mi][3],
                             bfh[ng][rp], bfh[ng][rp + 1]);
                }
        }
    }

    #pragma unroll
    for (int mi = 0; mi < 4; mi++) {
        int row = m0 + warp_m * 64 + mi * 16 + (lid >> 2);
        #pragma unroll
        for (int ni = 0; ni < 4; ni++) {
            int col = n0 + warp_n * 32 + ni * 8 + (lid & 3) * 2;
            *(float2*)&C[(size_t)row * N + col] = make_float2(acc[mi][ni][0], acc[mi][ni][1]);
            *(float2*)&C[(size_t)(row + 8) * N + col] = make_float2(acc[mi][ni][2], acc[mi][ni][3]);
        }
    }
}

// ============ bf16x3 GEMM 128x256, warp tile 64x64 (for Q/O) ============
// Higher MMA:LDSM ratio (6 vs 3) to relieve the shared-load bottleneck.
#define NSTB    4
#define A_TB    8192              // 128x32 bf16
#define B_TB    16384             // 256x32 bf16
#define STAGE_BB (2 * A_TB + 2 * B_TB)   // 48KB
#define BIG_SMEM (NSTB * STAGE_BB)       // 192KB

__global__ __launch_bounds__(256, 1) void gemm3_big_kernel(
    const __nv_bfloat16* __restrict__ Ah, const __nv_bfloat16* __restrict__ Al,
    const __nv_bfloat16* __restrict__ Bh, const __nv_bfloat16* __restrict__ Bl,
    float* __restrict__ C, int M, int N, int K)
{
    extern __shared__ char smem[];
    const uint32_t sb = smem_u32(smem);
    const int tid = threadIdx.x, wid = tid >> 5, lid = tid & 31;
    const int m0 = blockIdx.y * 128, n0 = blockIdx.x * 256;
    const int warp_m = wid & 1, warp_n = wid >> 1;   // 2 x 4, warp tile 64x64
    const int NCH = K / KC;

    uint32_t rel_a[4][2], rel_b[4][2];
    {
        uint32_t ar = (uint32_t)(warp_m * 64 + (lid & 15));
        uint32_t au = (uint32_t)(lid >> 4);
        #pragma unroll
        for (int mi = 0; mi < 4; mi++)
            #pragma unroll
            for (int k16 = 0; k16 < 2; k16++)
                rel_a[mi][k16] = swz(ar + mi * 16, au + k16 * 2);
        uint32_t br = (uint32_t)(warp_n * 64 + (lid & 7) + ((lid >> 4) << 3));
        uint32_t bu = (uint32_t)((lid >> 3) & 1);
        #pragma unroll
        for (int ng = 0; ng < 4; ng++)
            #pragma unroll
            for (int k16 = 0; k16 < 2; k16++)
                rel_b[ng][k16] = swz(br + ng * 16, bu + k16 * 2);
    }

    float acc[4][8][4];
    #pragma unroll
    for (int mi = 0; mi < 4; mi++)
        #pragma unroll
        for (int ni = 0; ni < 8; ni++)
            #pragma unroll
            for (int j = 0; j < 4; j++) acc[mi][ni][j] = 0.f;

    auto load_stage = [&](int s, int chunk) {
        const int k0 = chunk * KC;
        const uint32_t st = sb + s * STAGE_BB;
        #pragma unroll
        for (int t = 0; t < 12; t++) {
            int g = t * 256 + tid;          // 0..3071 16B units
            uint32_t dst;
            const __nv_bfloat16* src;
            if (g < 1024) {
                int r = (g & 511) >> 2, u = g & 3;
                dst = st + (g >> 9) * A_TB + swz(r, u);
                src = ((g >> 9) ? Al : Ah) + (size_t)(m0 + r) * K + k0 + u * 8;
            } else {
                int w = g - 1024;
                int r = (w & 1023) >> 2, u = w & 3;
                dst = st + 2 * A_TB + (w >> 10) * B_TB + swz(r, u);
                src = ((w >> 10) ? Bl : Bh) + (size_t)(n0 + r) * K + k0 + u * 8;
            }
            CP_ASYNC16(dst, src);
        }
    };

    load_stage(0, 0); CP_COMMIT();
    load_stage(1, 1); CP_COMMIT();
    load_stage(2, 2); CP_COMMIT();

    for (int i = 0; i < NCH; i++) {
        CP_WAIT2();
        __syncthreads();
        int nxt = i + NSTB - 1;
        if (nxt < NCH) load_stage(nxt % NSTB, nxt);
        CP_COMMIT();

        const uint32_t st = sb + (i % NSTB) * STAGE_BB;
        const uint32_t ah_b = st, al_b = st + A_TB;
        const uint32_t bh_b = st + 2 * A_TB, bl_b = st + 2 * A_TB + B_TB;

        #pragma unroll
        for (int k16 = 0; k16 < 2; k16++) {
            uint32_t afh[4][4], afl[4][4];
            #pragma unroll
            for (int mi = 0; mi < 4; mi++) {
                LDSM4(afh[mi][0], afh[mi][1], afh[mi][2], afh[mi][3], ah_b + rel_a[mi][k16]);
                LDSM4(afl[mi][0], afl[mi][1], afl[mi][2], afl[mi][3], al_b + rel_a[mi][k16]);
            }
            #pragma unroll
            for (int ng = 0; ng < 4; ng++) {
                uint32_t bfh[4], bfl[4];
                LDSM4(bfh[0], bfh[1], bfh[2], bfh[3], bh_b + rel_b[ng][k16]);
                LDSM4(bfl[0], bfl[1], bfl[2], bfl[3], bl_b + rel_b[ng][k16]);
                #pragma unroll
                for (int mi = 0; mi < 4; mi++)
                    #pragma unroll
                    for (int rp = 0; rp < 2; rp++) {
                        float* a = acc[mi][ng * 2 + rp];
                        MMA16816(a, afh[mi][0], afh[mi][1], afh[mi][2], afh[mi][3],
                                 bfh[rp * 2], bfh[rp * 2 + 1]);
                        MMA16816(a, afh[mi][0], afh[mi][1], afh[mi][2], afh[mi][3],
                                 bfl[rp * 2], bfl[rp * 2 + 1]);
                        MMA16816(a, afl[mi][0], afl[mi][1], afl[mi][2], afl[mi][3],
                                 bfh[rp * 2], bfh[rp * 2 + 1]);
                    }
            }
        }
    }

    #pragma unroll
    for (int mi = 0; mi < 4; mi++) {
        int row = m0 + warp_m * 64 + mi * 16 + (lid >> 2);
        #pragma unroll
        for (int ni = 0; ni < 8; ni++) {
            int col = n0 + warp_n * 64 + ni * 8 + (lid & 3) * 2;
            *(float2*)&C[(size_t)row * N + col] = make_float2(acc[mi][ni][0], acc[mi][ni][1]);
            *(float2*)&C[(size_t)(row + 8) * N + col] = make_float2(acc[mi][ni][2], acc[mi][ni][3]);
        }
    }
}

// ================= RoPE (exact reference semantics) =================
__global__ void rope_kernel(float* __restrict__ data, int cols, int total_pairs,
                            const int* __restrict__ sp)
{
    int idx = blockIdx.x * blockDim.x + threadIdx.x;
    if (idx >= total_pairs) return;
    int halfcols = cols >> 1;
    int row = idx / halfcols;
    int p   = idx - row * halfcols;
    int c0  = p * 2;
    int j0  = c0 & (HDIM - 1);
    int start = (sp == nullptr) ? 0 : *sp;
    float t = (float)(start + (row & (T_SEQ - 1)));
    const float lf = 9.210340371976184f;
    float a0 = t * expf(-(float)(j0 & 63)       * (lf / 64.f));
    float a1 = t * expf(-(float)((j0 + 1) & 63) * (lf / 64.f));
    float c0v, s0v, c1v, s1v;
    sincosf(a0, &s0v, &c0v);
    sincosf(a1, &s1v, &c1v);
    float* base = data + (size_t)row * cols + c0;
    float x0 = base[0], x1 = base[1];
    base[0] = x0 * c0v - x1 * s0v;
    base[1] = x1 * c1v + x0 * s1v;
}

// ================= Flash attention (causal, GQA), fp32 =================
__global__ __launch_bounds__(256) void attn_kernel(
    const float* __restrict__ Q, const float* __restrict__ K,
    const float* __restrict__ V, float* __restrict__ O)
{
    __shared__ float Ks[32 * 132];
    __shared__ float Vs[32 * 132];
    const int b  = blockIdx.z;
    const int h  = blockIdx.y;
    const int m0 = blockIdx.x * 64;
    const int kvh = h >> 2;
    const int tid = threadIdx.x;
    const int q4 = tid & 3;
    const int r  = tid >> 2;
    const int qpos = m0 + r;
    const float scale = 0.08838834764831845f;

    float qreg[32];
    {
        const float* qp = Q + (size_t)(b * T_SEQ + qpos) * 4096 + h * HDIM + q4 * 32;
        #pragma unroll
        for (int i = 0; i < 8; i++) {
            float4 v = *(const float4*)(qp + i * 4);
            qreg[i * 4 + 0] = v.x * scale; qreg[i * 4 + 1] = v.y * scale;
            qreg[i * 4 + 2] = v.z * scale; qreg[i * 4 + 3] = v.w * scale;
        }
    }
    float m_i = -INFINITY, l_i = 0.f;
    float acc[32];
    #pragma unroll
    for (int d = 0; d < 32; d++) acc[d] = 0.f;

    const int ktiles = m0 / 32 + 2;
    for (int it = 0; it < ktiles; it++) {
        const int kt = it * 32;
        #pragma unroll
        for (int i = 0; i < 4; i++) {
            int idx4 = tid + i * 256;
            int kk = idx4 >> 5, c4 = idx4 & 31;
            int gofs = (b * T_SEQ + kt + kk) * 1024 + kvh * HDIM + c4 * 4;
            float4 kv4 = *(const float4*)&K[gofs];
            float4 vv4 = *(const float4*)&V[gofs];
            int sofs = kk * 132 + (c4 >> 3) * 33 + (c4 & 7) * 4;
            Ks[sofs + 0] = kv4.x; Ks[sofs + 1] = kv4.y;
            Ks[sofs + 2] = kv4.z; Ks[sofs + 3] = kv4.w;
            Vs[sofs + 0] = vv4.x; Vs[sofs + 1] = vv4.y;
            Vs[sofs + 2] = vv4.z; Vs[sofs + 3] = vv4.w;
        }
        __syncthreads();

        float s[32];
        #pragma unroll
        for (int kk = 0; kk < 32; kk++) {
            const float* kp = &Ks[kk * 132 + q4 * 33];
            float s0 = 0.f, s1 = 0.f, s2 = 0.f, s3 = 0.f;
            #pragma unroll
            for (int d = 0; d < 32; d += 4) {
                s0 += qreg[d + 0] * kp[d + 0];
                s1 += qreg[d + 1] * kp[d + 1];
                s2 += qreg[d + 2] * kp[d + 2];
                s3 += qreg[d + 3] * kp[d + 3];
            }
            float sum = (s0 + s1) + (s2 + s3);
            sum += __shfl_xor_sync(0xFFFFFFFFu, sum, 1);
            sum += __shfl_xor_sync(0xFFFFFFFFu, sum, 2);
            s[kk] = (kt + kk <= qpos) ? sum : -INFINITY;
        }
        float mnew = m_i;
        #pragma unroll
        for (int kk = 0; kk < 32; kk++) mnew = fmaxf(mnew, s[kk]);
        float corr = __expf(m_i - mnew);
        float psum = 0.f;
        #pragma unroll
        for (int kk = 0; kk < 32; kk++) { s[kk] = __expf(s[kk] - mnew); psum += s[kk]; }
        l_i = l_i * corr + psum;
        m_i = mnew;
        #pragma unroll
        for (int d = 0; d < 32; d++) acc[d] *= corr;
        #pragma unroll
        for (int kk = 0; kk < 32; kk++) {
            const float* vp = &Vs[kk * 132 + q4 * 33];
            float pv = s[kk];
            #pragma unroll
            for (int d = 0; d < 32; d++) acc[d] += pv * vp[d];
        }
        __syncthreads();
    }
    float inv = 1.0f / l_i;
    float* op = O + (size_t)(b * T_SEQ + qpos) * 4096 + h * HDIM + q4 * 32;
    #pragma unroll
    for (int i = 0; i < 8; i++) {
        float4 v;
        v.x = acc[i * 4 + 0] * inv; v.y = acc[i * 4 + 1] * inv;
        v.z = acc[i * 4 + 2] * inv; v.w = acc[i * 4 + 3] * inv;
        *(float4*)(op + i * 4) = v;
    }
}

// ================= launcher =================
extern "C" void kernel_launch(void* const* d_in, const int* in_sizes, int n_in,
                              void* d_out, int out_size)
{
    const float* x  = (const float*)d_in[0];
    const float* wq = (const float*)d_in[1];
    const float* wk = (const float*)d_in[2];
    const float* wv = (const float*)d_in[3];
    const float* wo = (const float*)d_in[4];
    const int*   sp = (n_in > 5) ? (const int*)d_in[5] : nullptr;
    float* out = (float*)d_out;
    (void)in_sizes; (void)out_size;

    float *gq, *gk, *gv, *ga;
    cudaGetSymbolAddress((void**)&gq, g_q);
    cudaGetSymbolAddress((void**)&gk, g_k);
    cudaGetSymbolAddress((void**)&gv, g_v);
    cudaGetSymbolAddress((void**)&ga, g_attn);
    __nv_bfloat16 *xh, *xl, *ah, *al, *wqh, *wql, *wkh, *wkl, *wvh, *wvl, *woh, *wol;
    cudaGetSymbolAddress((void**)&xh, g_xh);   cudaGetSymbolAddress((void**)&xl, g_xl);
    cudaGetSymbolAddress((void**)&ah, g_ah);   cudaGetSymbolAddress((void**)&al, g_al);
    cudaGetSymbolAddress((void**)&wqh, g_wqh); cudaGetSymbolAddress((void**)&wql, g_wql);
    cudaGetSymbolAddress((void**)&wkh, g_wkh); cudaGetSymbolAddress((void**)&wkl, g_wkl);
    cudaGetSymbolAddress((void**)&wvh, g_wvh); cudaGetSymbolAddress((void**)&wvl, g_wvl);
    cudaGetSymbolAddress((void**)&woh, g_woh); cudaGetSymbolAddress((void**)&wol, g_wol);

    cudaFuncSetAttribute(gemm3_kernel, cudaFuncAttributeMaxDynamicSharedMemorySize, GEMM_SMEM);
    cudaFuncSetAttribute(gemm3_big_kernel, cudaFuncAttributeMaxDynamicSharedMemorySize, BIG_SMEM);

    // split x; transpose-split weights
    int n4x = BT * 4096 / 4;
    split_kernel<<<n4x / 256, 256>>>(x, xh, xl, n4x);
    tsplit_kernel<<<dim3(4096 / 32, 4096 / 32), 256>>>(wq, wqh, wql, 4096, 4096);
    tsplit_kernel<<<dim3(1024 / 32, 4096 / 32), 256>>>(wk, wkh, wkl, 4096, 1024);
    tsplit_kernel<<<dim3(1024 / 32, 4096 / 32), 256>>>(wv, wvh, wvl, 4096, 1024);
    tsplit_kernel<<<dim3(4096 / 32, 4096 / 32), 256>>>(wo, woh, wol, 4096, 4096);

    // projections on tensor cores
    gemm3_big_kernel<<<dim3(4096 / 256, BT / 128), 256, BIG_SMEM>>>(xh, xl, wqh, wql, gq, BT, 4096, 4096);
    gemm3_kernel<<<dim3(1024 / 128, BT / 128), 256, GEMM_SMEM>>>(xh, xl, wkh, wkl, gk, BT, 1024, 4096);
    gemm3_kernel<<<dim3(1024 / 128, BT / 128), 256, GEMM_SMEM>>>(xh, xl, wvh, wvl, gv, BT, 1024, 4096);

    // RoPE
    rope_kernel<<<(BT * 2048) / 256, 256>>>(gq, 4096, BT * 2048, sp);
    rope_kernel<<<(BT * 512) / 256, 256>>>(gk, 1024, BT * 512, sp);

    // attention
    attn_kernel<<<dim3(T_SEQ / 64, NH, B_SZ), 256>>>(gq, gk, gv, ga);

    // output projection
    split_kernel<<<n4x / 256, 256>>>(ga, ah, al, n4x);
    gemm3_big_kernel<<<dim3(4096 / 256, BT / 128), 256, BIG_SMEM>>>(ah, al, woh, wol, out, BT, 4096, 4096);
}

// round 7
// speedup vs baseline: 3.5757x; 1.6845x over previous
#include <cuda_runtime.h>
#include <cuda_bf16.h>
#include <math.h>
#include <stdint.h>

#define B_SZ   2
#define T_SEQ  1024
#define BT     2048
#define NH     32
#define HDIM   128

// ================= scratch =================
__device__ float g_q[BT * 4096];
__device__ float g_k[BT * 1024];
__device__ float g_v[BT * 1024];
__device__ float g_attn[BT * 4096];
__device__ __nv_bfloat16 g_xh[BT * 4096], g_xl[BT * 4096];
__device__ __nv_bfloat16 g_ah[BT * 4096], g_al[BT * 4096];
__device__ __nv_bfloat16 g_qh[BT * 4096], g_ql[BT * 4096];
__device__ __nv_bfloat16 g_kh[BT * 1024], g_kl[BT * 1024];
__device__ __nv_bfloat16 g_vh[BT * 1024], g_vl[BT * 1024];
__device__ __nv_bfloat16 g_wqh[4096 * 4096], g_wql[4096 * 4096];
__device__ __nv_bfloat16 g_wkh[4096 * 1024], g_wkl[4096 * 1024];
__device__ __nv_bfloat16 g_wvh[4096 * 1024], g_wvl[4096 * 1024];
__device__ __nv_bfloat16 g_woh[4096 * 4096], g_wol[4096 * 4096];

// ================= helpers =================
__device__ __forceinline__ uint32_t smem_u32(const void* p) {
    uint32_t a;
    asm("{ .reg .u64 t; cvta.to.shared.u64 t, %1; cvt.u32.u64 %0, t; }"
        : "=r"(a) : "l"(p));
    return a;
}
// GEMM tile swizzle: (rows)x32(k) bf16 tile
__device__ __forceinline__ uint32_t swz(uint32_t r, uint32_t u) {
    return ((r >> 1) << 7) | (((((r & 1) << 2) | u) ^ ((r >> 1) & 7)) << 4);
}
// attention tile swizzle: (rows)x128 bf16 tile, 16 16B-units/row
#define OFFA(r, u) (((uint32_t)(r)) * 256 + ((((uint32_t)(u)) ^ (((uint32_t)(r)) & 7)) << 4))

#define CP_ASYNC16(dst, src) \
    asm volatile("cp.async.cg.shared.global [%0], [%1], 16;" :: "r"(dst), "l"(src))
#define CP_COMMIT() asm volatile("cp.async.commit_group;" ::: "memory")
#define CP_WAIT0()  asm volatile("cp.async.wait_group 0;" ::: "memory")
#define CP_WAIT1()  asm volatile("cp.async.wait_group 1;" ::: "memory")
#define CP_WAIT2()  asm volatile("cp.async.wait_group 2;" ::: "memory")

#define LDSM4(r0, r1, r2, r3, a) \
    asm volatile("ldmatrix.sync.aligned.m8n8.x4.shared.b16 {%0,%1,%2,%3}, [%4];" \
        : "=r"(r0), "=r"(r1), "=r"(r2), "=r"(r3) : "r"(a))
#define LDSM4T(r0, r1, r2, r3, a) \
    asm volatile("ldmatrix.sync.aligned.m8n8.x4.trans.shared.b16 {%0,%1,%2,%3}, [%4];" \
        : "=r"(r0), "=r"(r1), "=r"(r2), "=r"(r3) : "r"(a))

#define MMA16816(c, a0, a1, a2, a3, b0, b1) \
    asm volatile("mma.sync.aligned.m16n8k16.row.col.f32.bf16.bf16.f32 " \
        "{%0,%1,%2,%3}, {%4,%5,%6,%7}, {%8,%9}, {%0,%1,%2,%3};" \
        : "+f"((c)[0]), "+f"((c)[1]), "+f"((c)[2]), "+f"((c)[3]) \
        : "r"(a0), "r"(a1), "r"(a2), "r"(a3), "r"(b0), "r"(b1))

__device__ __forceinline__ void pack_hl(float f0, float f1, uint32_t& h, uint32_t& l) {
    __nv_bfloat162 hh = __floats2bfloat162_rn(f0, f1);
    float r0 = f0 - __bfloat162float(hh.x);
    float r1 = f1 - __bfloat162float(hh.y);
    __nv_bfloat162 ll = __floats2bfloat162_rn(r0, r1);
    h = *(uint32_t*)&hh;
    l = *(uint32_t*)&ll;
}

// ============ split fp32 -> bf16 hi/lo (row-major) ============
__global__ void split_kernel(const float* __restrict__ in,
                             __nv_bfloat16* __restrict__ hi,
                             __nv_bfloat16* __restrict__ lo, int n4)
{
    int i = blockIdx.x * blockDim.x + threadIdx.x;
    if (i >= n4) return;
    float4 v = ((const float4*)in)[i];
    __nv_bfloat16 h0 = __float2bfloat16(v.x);
    __nv_bfloat16 h1 = __float2bfloat16(v.y);
    __nv_bfloat16 h2 = __float2bfloat16(v.z);
    __nv_bfloat16 h3 = __float2bfloat16(v.w);
    __nv_bfloat162* hp = (__nv_bfloat162*)hi;
    __nv_bfloat162* lp = (__nv_bfloat162*)lo;
    hp[2 * i]     = __nv_bfloat162(h0, h1);
    hp[2 * i + 1] = __nv_bfloat162(h2, h3);
    lp[2 * i]     = __nv_bfloat162(__float2bfloat16(v.x - __bfloat162float(h0)),
                                   __float2bfloat16(v.y - __bfloat162float(h1)));
    lp[2 * i + 1] = __nv_bfloat162(__float2bfloat16(v.z - __bfloat162float(h2)),
                                   __float2bfloat16(v.w - __bfloat162float(h3)));
}

// ============ transpose + split: W[K][N] fp32 -> Wt[N][K] bf16 hi/lo ============
__global__ __launch_bounds__(256) void tsplit_kernel(
    const float* __restrict__ W, __nv_bfloat16* __restrict__ hi,
    __nv_bfloat16* __restrict__ lo, int K, int N)
{
    __shared__ float s[32][33];
    const int n0 = blockIdx.x * 32, k0 = blockIdx.y * 32;
    const int c = threadIdx.x & 31, r0 = threadIdx.x >> 5;
    #pragma unroll
    for (int rr = 0; rr < 4; rr++) {
        int r = r0 + rr * 8;
        s[r][c] = W[(size_t)(k0 + r) * N + n0 + c];
    }
    __syncthreads();
    #pragma unroll
    for (int rr = 0; rr < 4; rr++) {
        int r = r0 + rr * 8;
        float v = s[c][r];
        __nv_bfloat16 h = __float2bfloat16(v);
        size_t o = (size_t)(n0 + r) * K + k0 + c;
        hi[o] = h;
        lo[o] = __float2bfloat16(v - __bfloat162float(h));
    }
}

// ============ RoPE + split: fp32 in, roped bf16 hi/lo out ============
__global__ void rope_split_kernel(const float* __restrict__ in,
                                  __nv_bfloat16* __restrict__ hi,
                                  __nv_bfloat16* __restrict__ lo,
                                  int cols, int total_pairs,
                                  const int* __restrict__ sp, float scale)
{
    int idx = blockIdx.x * blockDim.x + threadIdx.x;
    if (idx >= total_pairs) return;
    int halfcols = cols >> 1;
    int row = idx / halfcols;
    int p   = idx - row * halfcols;
    int c0  = p * 2;
    int j0  = c0 & (HDIM - 1);
    int start = (sp == nullptr) ? 0 : *sp;
    float t = (float)(start + (row & (T_SEQ - 1)));
    const float lf = 9.210340371976184f;
    float a0 = t * expf(-(float)(j0 & 63)       * (lf / 64.f));
    float a1 = t * expf(-(float)((j0 + 1) & 63) * (lf / 64.f));
    float c0v, s0v, c1v, s1v;
    sincosf(a0, &s0v, &c0v);
    sincosf(a1, &s1v, &c1v);
    const float* base = in + (size_t)row * cols + c0;
    float x0 = base[0], x1 = base[1];
    float y0 = (x0 * c0v - x1 * s0v) * scale;
    float y1 = (x1 * c1v + x0 * s1v) * scale;
    uint32_t h, l;
    pack_hl(y0, y1, h, l);
    *(uint32_t*)(hi + (size_t)row * cols + c0) = h;
    *(uint32_t*)(lo + (size_t)row * cols + c0) = l;
}

// ============ bf16x3 GEMM 128x128 (for K/V): C = A @ Bt^T ============
#define KC      32
#define NSTAGE  3
#define TILE_B  8192
#define STAGE_B (4 * TILE_B)
#define GEMM_SMEM (NSTAGE * STAGE_B)

__global__ __launch_bounds__(256, 1) void gemm3_kernel(
    const __nv_bfloat16* __restrict__ Ah, const __nv_bfloat16* __restrict__ Al,
    const __nv_bfloat16* __restrict__ Bh, const __nv_bfloat16* __restrict__ Bl,
    float* __restrict__ C, int M, int N, int K)
{
    extern __shared__ char smem[];
    const uint32_t sb = smem_u32(smem);
    const int tid = threadIdx.x, wid = tid >> 5, lid = tid & 31;
    const int m0 = blockIdx.y * 128, n0 = blockIdx.x * 128;
    const int warp_m = wid & 1, warp_n = wid >> 1;
    const int NCH = K / KC;

    uint32_t rel_a[4][2], rel_b[2][2];
    {
        uint32_t ar = (uint32_t)(warp_m * 64 + (lid & 15));
        uint32_t au = (uint32_t)(lid >> 4);
        #pragma unroll
        for (int mi = 0; mi < 4; mi++)
            #pragma unroll
            for (int k16 = 0; k16 < 2; k16++)
                rel_a[mi][k16] = swz(ar + mi * 16, au + k16 * 2);
        uint32_t br = (uint32_t)(warp_n * 32 + (lid & 7) + ((lid >> 4) << 3));
        uint32_t bu = (uint32_t)((lid >> 3) & 1);
        #pragma unroll
        for (int ng = 0; ng < 2; ng++)
            #pragma unroll
            for (int k16 = 0; k16 < 2; k16++)
                rel_b[ng][k16] = swz(br + ng * 16, bu + k16 * 2);
    }

    float acc[4][4][4];
    #pragma unroll
    for (int mi = 0; mi < 4; mi++)
        #pragma unroll
        for (int ni = 0; ni < 4; ni++)
            #pragma unroll
            for (int j = 0; j < 4; j++) acc[mi][ni][j] = 0.f;

    auto load_stage = [&](int s, int chunk) {
        const int k0 = chunk * KC;
        const uint32_t st = sb + s * STAGE_B;
        #pragma unroll
        for (int t = 0; t < 8; t++) {
            int g = t * 256 + tid;
            int tile = g >> 9;
            int w = g & 511;
            int r = w >> 2, u = w & 3;
            uint32_t dst = st + tile * TILE_B + swz(r, u);
            const __nv_bfloat16* src;
            if (tile == 0)      src = Ah + (size_t)(m0 + r) * K + k0 + u * 8;
            else if (tile == 1) src = Al + (size_t)(m0 + r) * K + k0 + u * 8;
            else if (tile == 2) src = Bh + (size_t)(n0 + r) * K + k0 + u * 8;
            else                src = Bl + (size_t)(n0 + r) * K + k0 + u * 8;
            CP_ASYNC16(dst, src);
        }
    };

    load_stage(0, 0); CP_COMMIT();
    load_stage(1, 1); CP_COMMIT();

    for (int i = 0; i < NCH; i++) {
        CP_WAIT1();
        __syncthreads();
        int nxt = i + NSTAGE - 1;
        if (nxt < NCH) load_stage(nxt % NSTAGE, nxt);
        CP_COMMIT();

        const uint32_t st = sb + (i % NSTAGE) * STAGE_B;
        const uint32_t ah_b = st, al_b = st + TILE_B;
        const uint32_t bh_b = st + 2 * TILE_B, bl_b = st + 3 * TILE_B;

        #pragma unroll
        for (int k16 = 0; k16 < 2; k16++) {
            uint32_t afh[4][4], afl[4][4], bfh[2][4], bfl[2][4];
            #pragma unroll
            for (int mi = 0; mi < 4; mi++) {
                LDSM4(afh[mi][0], afh[mi][1], afh[mi][2], afh[mi][3], ah_b + rel_a[mi][k16]);
                LDSM4(afl[mi][0], afl[mi][1], afl[mi][2], afl[mi][3], al_b + rel_a[mi][k16]);
            }
            #pragma unroll
            for (int ng = 0; ng < 2; ng++) {
                LDSM4(bfh[ng][0], bfh[ng][1], bfh[ng][2], bfh[ng][3], bh_b + rel_b[ng][k16]);
                LDSM4(bfl[ng][0], bfl[ng][1], bfl[ng][2], bfl[ng][3], bl_b + rel_b[ng][k16]);
            }
            #pragma unroll
            for (int mi = 0; mi < 4; mi++)
                #pragma unroll
                for (int ni = 0; ni < 4; ni++) {
                    int ng = ni >> 1, rp = (ni & 1) * 2;
                    MMA16816(acc[mi][ni], afh[mi][0], afh[mi][1], afh[mi][2], afh[mi][3],
                             bfh[ng][rp], bfh[ng][rp + 1]);
                    MMA16816(acc[mi][ni], afh[mi][0], afh[mi][1], afh[mi][2], afh[mi][3],
                             bfl[ng][rp], bfl[ng][rp + 1]);
                    MMA16816(acc[mi][ni], afl[mi][0], afl[mi][1], afl[mi][2], afl[mi][3],
                             bfh[ng][rp], bfh[ng][rp + 1]);
                }
        }
    }

    #pragma unroll
    for (int mi = 0; mi < 4; mi++) {
        int row = m0 + warp_m * 64 + mi * 16 + (lid >> 2);
        #pragma unroll
        for (int ni = 0; ni < 4; ni++) {
            int col = n0 + warp_n * 32 + ni * 8 + (lid & 3) * 2;
            *(float2*)&C[(size_t)row * N + col] = make_float2(acc[mi][ni][0], acc[mi][ni][1]);
            *(float2*)&C[(size_t)(row + 8) * N + col] = make_float2(acc[mi][ni][2], acc[mi][ni][3]);
        }
    }
}

// ============ bf16x3 GEMM 128x256 (for Q/O) ============
#define NSTB    4
#define A_TB    8192
#define B_TB    16384
#define STAGE_BB (2 * A_TB + 2 * B_TB)
#define BIG_SMEM (NSTB * STAGE_BB)

__global__ __launch_bounds__(256, 1) void gemm3_big_kernel(
    const __nv_bfloat16* __restrict__ Ah, const __nv_bfloat16* __restrict__ Al,
    const __nv_bfloat16* __restrict__ Bh, const __nv_bfloat16* __restrict__ Bl,
    float* __restrict__ C, int M, int N, int K)
{
    extern __shared__ char smem[];
    const uint32_t sb = smem_u32(smem);
    const int tid = threadIdx.x, wid = tid >> 5, lid = tid & 31;
    const int m0 = blockIdx.y * 128, n0 = blockIdx.x * 256;
    const int warp_m = wid & 1, warp_n = wid >> 1;
    const int NCH = K / KC;

    uint32_t rel_a[4][2], rel_b[4][2];
    {
        uint32_t ar = (uint32_t)(warp_m * 64 + (lid & 15));
        uint32_t au = (uint32_t)(lid >> 4);
        #pragma unroll
        for (int mi = 0; mi < 4; mi++)
            #pragma unroll
            for (int k16 = 0; k16 < 2; k16++)
                rel_a[mi][k16] = swz(ar + mi * 16, au + k16 * 2);
        uint32_t br = (uint32_t)(warp_n * 64 + (lid & 7) + ((lid >> 4) << 3));
        uint32_t bu = (uint32_t)((lid >> 3) & 1);
        #pragma unroll
        for (int ng = 0; ng < 4; ng++)
            #pragma unroll
            for (int k16 = 0; k16 < 2; k16++)
                rel_b[ng][k16] = swz(br + ng * 16, bu + k16 * 2);
    }

    float acc[4][8][4];
    #pragma unroll
    for (int mi = 0; mi < 4; mi++)
        #pragma unroll
        for (int ni = 0; ni < 8; ni++)
            #pragma unroll
            for (int j = 0; j < 4; j++) acc[mi][ni][j] = 0.f;

    auto load_stage = [&](int s, int chunk) {
        const int k0 = chunk * KC;
        const uint32_t st = sb + s * STAGE_BB;
        #pragma unroll
        for (int t = 0; t < 12; t++) {
            int g = t * 256 + tid;
            uint32_t dst;
            const __nv_bfloat16* src;
            if (g < 1024) {
                int r = (g & 511) >> 2, u = g & 3;
                dst = st + (g >> 9) * A_TB + swz(r, u);
                src = ((g >> 9) ? Al : Ah) + (size_t)(m0 + r) * K + k0 + u * 8;
            } else {
                int w = g - 1024;
                int r = (w & 1023) >> 2, u = w & 3;
                dst = st + 2 * A_TB + (w >> 10) * B_TB + swz(r, u);
                src = ((w >> 10) ? Bl : Bh) + (size_t)(n0 + r) * K + k0 + u * 8;
            }
            CP_ASYNC16(dst, src);
        }
    };

    load_stage(0, 0); CP_COMMIT();
    load_stage(1, 1); CP_COMMIT();
    load_stage(2, 2); CP_COMMIT();

    for (int i = 0; i < NCH; i++) {
        CP_WAIT2();
        __syncthreads();
        int nxt = i + NSTB - 1;
        if (nxt < NCH) load_stage(nxt % NSTB, nxt);
        CP_COMMIT();

        const uint32_t st = sb + (i % NSTB) * STAGE_BB;
        const uint32_t ah_b = st, al_b = st + A_TB;
        const uint32_t bh_b = st + 2 * A_TB, bl_b = st + 2 * A_TB + B_TB;

        #pragma unroll
        for (int k16 = 0; k16 < 2; k16++) {
            uint32_t afh[4][4], afl[4][4];
            #pragma unroll
            for (int mi = 0; mi < 4; mi++) {
                LDSM4(afh[mi][0], afh[mi][1], afh[mi][2], afh[mi][3], ah_b + rel_a[mi][k16]);
                LDSM4(afl[mi][0], afl[mi][1], afl[mi][2], afl[mi][3], al_b + rel_a[mi][k16]);
            }
            #pragma unroll
            for (int ng = 0; ng < 4; ng++) {
                uint32_t bfh[4], bfl[4];
                LDSM4(bfh[0], bfh[1], bfh[2], bfh[3], bh_b + rel_b[ng][k16]);
                LDSM4(bfl[0], bfl[1], bfl[2], bfl[3], bl_b + rel_b[ng][k16]);
                #pragma unroll
                for (int mi = 0; mi < 4; mi++)
                    #pragma unroll
                    for (int rp = 0; rp < 2; rp++) {
                        float* a = acc[mi][ng * 2 + rp];
                        MMA16816(a, afh[mi][0], afh[mi][1], afh[mi][2], afh[mi][3],
                                 bfh[rp * 2], bfh[rp * 2 + 1]);
                        MMA16816(a, afh[mi][0], afh[mi][1], afh[mi][2], afh[mi][3],
                                 bfl[rp * 2], bfl[rp * 2 + 1]);
                        MMA16816(a, afl[mi][0], afl[mi][1], afl[mi][2], afl[mi][3],
                                 bfh[rp * 2], bfh[rp * 2 + 1]);
                    }
            }
        }
    }

    #pragma unroll
    for (int mi = 0; mi < 4; mi++) {
        int row = m0 + warp_m * 64 + mi * 16 + (lid >> 2);
        #pragma unroll
        for (int ni = 0; ni < 8; ni++) {
            int col = n0 + warp_n * 64 + ni * 8 + (lid & 3) * 2;
            *(float2*)&C[(size_t)row * N + col] = make_float2(acc[mi][ni][0], acc[mi][ni][1]);
            *(float2*)&C[(size_t)(row + 8) * N + col] = make_float2(acc[mi][ni][2], acc[mi][ni][3]);
        }
    }
}

// ============ Tensor-core flash attention (causal, GQA, bf16x3) ============
// CTA: 128 q-rows, 8 warps (m16 each). KV tile 64. 2-stage cp.async pipeline.
// smem: [0,64K) = Q hi/lo then KV odd stages; [64K,128K) = KV even stages.
#define ATT_SMEM 131072

__global__ __launch_bounds__(256, 1) void attn_tc_kernel(
    const __nv_bfloat16* __restrict__ Qh, const __nv_bfloat16* __restrict__ Ql,
    const __nv_bfloat16* __restrict__ Kh, const __nv_bfloat16* __restrict__ Kl,
    const __nv_bfloat16* __restrict__ Vh, const __nv_bfloat16* __restrict__ Vl,
    float* __restrict__ Out)
{
    extern __shared__ char smem[];
    const uint32_t sb = smem_u32(smem);
    const int tid = threadIdx.x, wid = tid >> 5, lid = tid & 31;
    const int b = blockIdx.z, h = blockIdx.y, m0 = blockIdx.x * 128;
    const int kvh = h >> 2;

    // --- Q load into region A (hi @0, lo @32K) ---
    #pragma unroll
    for (int i = 0; i < 16; i++) {
        int idx = i * 256 + tid;
        int t = idx >> 11, w = idx & 2047;
        int r = w >> 4, u = w & 15;
        const __nv_bfloat16* src = (t ? Ql : Qh)
            + (size_t)(b * T_SEQ + m0 + r) * 4096 + h * HDIM + u * 8;
        CP_ASYNC16(sb + t * 32768 + OFFA(r, u), src);
    }
    CP_COMMIT();

    auto kvload = [&](int kt, uint32_t base) {
        #pragma unroll
        for (int i = 0; i < 16; i++) {
            int idx = i * 256 + tid;
            int t = idx >> 10, w = idx & 1023;
            int r = w >> 4, u = w & 15;
            const __nv_bfloat16* arr = (t == 0) ? Kh : (t == 1) ? Kl : (t == 2) ? Vh : Vl;
            const __nv_bfloat16* src = arr
                + (size_t)(b * T_SEQ + kt * 64 + r) * 1024 + kvh * HDIM + u * 8;
            CP_ASYNC16(sb + base + t * 16384 + OFFA(r, u), src);
        }
        CP_COMMIT();
    };

    const int nkt = (m0 + 128) / 64;
    kvload(0, 65536);

    CP_WAIT1();            // Q complete
    __syncthreads();

    // --- Q fragments (reg-resident) ---
    uint32_t qfh[8][4], qfl[8][4];
    {
        uint32_t r = (uint32_t)(wid * 16 + (lid & 15));
        uint32_t ub = (uint32_t)(lid >> 4);
        #pragma unroll
        for (int ks = 0; ks < 8; ks++) {
            uint32_t off = OFFA(r, ks * 2 + ub);
            LDSM4(qfh[ks][0], qfh[ks][1], qfh[ks][2], qfh[ks][3], sb + off);
            LDSM4(qfl[ks][0], qfl[ks][1], qfl[ks][2], qfl[ks][3], sb + 32768 + off);
        }
    }
    __syncthreads();       // region A free
    if (nkt > 1) kvload(1, 0);

    float oacc[16][4];
    #pragma unroll
    for (int f = 0; f < 16; f++)
        #pragma unroll
        for (int j = 0; j < 4; j++) oacc[f][j] = 0.f;
    float mr0 = -INFINITY, mr1 = -INFINITY, l0 = 0.f, l1 = 0.f;

    const int row_lo = m0 + wid * 16;
    const int r0 = row_lo + (lid >> 2);

    for (int it = 0; it < nkt; it++) {
        if (it + 1 < nkt) { CP_WAIT1(); } else { CP_WAIT0(); }
        __syncthreads();
        const uint32_t stg = sb + ((it & 1) ? 0u : 65536u);
        const int ktb = it * 64;

        if (ktb <= row_lo + 15) {   // skip fully-masked tiles for this warp
            // ---- S = Q K^T (bf16x3) ----
            float s[8][4];
            #pragma unroll
            for (int j = 0; j < 8; j++)
                #pragma unroll
                for (int q = 0; q < 4; q++) s[j][q] = 0.f;

            uint32_t br = (uint32_t)((lid & 7) + ((lid >> 4) << 3));
            uint32_t bu = (uint32_t)((lid >> 3) & 1);
            #pragma unroll
            for (int ks = 0; ks < 8; ks++) {
                #pragma unroll
                for (int jj = 0; jj < 4; jj++) {
                    uint32_t kh0, kh1, kh2, kh3, kl0, kl1, kl2, kl3;
                    uint32_t off = OFFA(jj * 16 + br, ks * 2 + bu);
                    LDSM4(kh0, kh1, kh2, kh3, stg + off);
                    LDSM4(kl0, kl1, kl2, kl3, stg + 16384 + off);
                    MMA16816(s[jj * 2],     qfh[ks][0], qfh[ks][1], qfh[ks][2], qfh[ks][3], kh0, kh1);
                    MMA16816(s[jj * 2 + 1], qfh[ks][0], qfh[ks][1], qfh[ks][2], qfh[ks][3], kh2, kh3);
                    MMA16816(s[jj * 2],     qfh[ks][0], qfh[ks][1], qfh[ks][2], qfh[ks][3], kl0, kl1);
                    MMA16816(s[jj * 2 + 1], qfh[ks][0], qfh[ks][1], qfh[ks][2], qfh[ks][3], kl2, kl3);
                    MMA16816(s[jj * 2],     qfl[ks][0], qfl[ks][1], qfl[ks][2], qfl[ks][3], kh0, kh1);
                    MMA16816(s[jj * 2 + 1], qfl[ks][0], qfl[ks][1], qfl[ks][2], qfl[ks][3], kh2, kh3);
                }
            }

            // ---- causal mask ----
            if (ktb + 63 > row_lo) {
                #pragma unroll
                for (int j = 0; j < 8; j++) {
                    int c = ktb + j * 8 + (lid & 3) * 2;
                    if (c > r0)         s[j][0] = -INFINITY;
                    if (c + 1 > r0)     s[j][1] = -INFINITY;
                    if (c > r0 + 8)     s[j][2] = -INFINITY;
                    if (c + 1 > r0 + 8) s[j][3] = -INFINITY;
                }
            }

            // ---- online softmax ----
            float mx0 = -INFINITY, mx1 = -INFINITY;
            #pragma unroll
            for (int j = 0; j < 8; j++) {
                mx0 = fmaxf(mx0, fmaxf(s[j][0], s[j][1]));
                mx1 = fmaxf(mx1, fmaxf(s[j][2], s[j][3]));
            }
            mx0 = fmaxf(mx0, __shfl_xor_sync(0xFFFFFFFFu, mx0, 1));
            mx0 = fmaxf(mx0, __shfl_xor_sync(0xFFFFFFFFu, mx0, 2));
            mx1 = fmaxf(mx1, __shfl_xor_sync(0xFFFFFFFFu, mx1, 1));
            mx1 = fmaxf(mx1, __shfl_xor_sync(0xFFFFFFFFu, mx1, 2));
            float mn0 = fmaxf(mr0, mx0), mn1 = fmaxf(mr1, mx1);
            float c0 = __expf(mr0 - mn0), c1 = __expf(mr1 - mn1);
            mr0 = mn0; mr1 = mn1;
            float rs0 = 0.f, rs1 = 0.f;
            #pragma unroll
            for (int j = 0; j < 8; j++) {
                s[j][0] = __expf(s[j][0] - mn0);
                s[j][1] = __expf(s[j][1] - mn0);
                s[j][2] = __expf(s[j][2] - mn1);
                s[j][3] = __expf(s[j][3] - mn1);
                rs0 += s[j][0] + s[j][1];
                rs1 += s[j][2] + s[j][3];
            }
            rs0 += __shfl_xor_sync(0xFFFFFFFFu, rs0, 1);
            rs0 += __shfl_xor_sync(0xFFFFFFFFu, rs0, 2);
            rs1 += __shfl_xor_sync(0xFFFFFFFFu, rs1, 1);
            rs1 += __shfl_xor_sync(0xFFFFFFFFu, rs1, 2);
            l0 = l0 * c0 + rs0;
            l1 = l1 * c1 + rs1;
            #pragma unroll
            for (int f = 0; f < 16; f++) {
                oacc[f][0] *= c0; oacc[f][1] *= c0;
                oacc[f][2] *= c1; oacc[f][3] *= c1;
            }

            // ---- O += P V (bf16x3 on P/V) ----
            #pragma unroll
            for (int ks2 = 0; ks2 < 4; ks2++) {
                int j0 = ks2 * 2, j1 = j0 + 1;
                uint32_t pah[4], pal[4];
                pack_hl(s[j0][0], s[j0][1], pah[0], pal[0]);
                pack_hl(s[j0][2], s[j0][3], pah[1], pal[1]);
                pack_hl(s[j1][0], s[j1][1], pah[2], pal[2]);
                pack_hl(s[j1][2], s[j1][3], pah[3], pal[3]);
                uint32_t vr = (uint32_t)(ks2 * 16 + (lid & 15));
                uint32_t vub = (uint32_t)(lid >> 4);
                #pragma unroll
                for (int ng = 0; ng < 8; ng++) {
                    uint32_t vh0, vh1, vh2, vh3, vl0, vl1, vl2, vl3;
                    uint32_t off = OFFA(vr, ng * 2 + vub);
                    LDSM4T(vh0, vh1, vh2, vh3, stg + 32768 + off);
                    LDSM4T(vl0, vl1, vl2, vl3, stg + 49152 + off);
                    MMA16816(oacc[ng * 2],     pah[0], pah[1], pah[2], pah[3], vh0, vh1);
                    MMA16816(oacc[ng * 2 + 1], pah[0], pah[1], pah[2], pah[3], vh2, vh3);
                    MMA16816(oacc[ng * 2],     pah[0], pah[1], pah[2], pah[3], vl0, vl1);
                    MMA16816(oacc[ng * 2 + 1], pah[0], pah[1], pah[2], pah[3], vl2, vl3);
                    MMA16816(oacc[ng * 2],     pal[0], pal[1], pal[2], pal[3], vh0, vh1);
                    MMA16816(oacc[ng * 2 + 1], pal[0], pal[1], pal[2], pal[3], vh2, vh3);
                }
            }
        }
        __syncthreads();
        // FIX (R5 bug): tile it+2 is consumed at iteration it+2, which reads
        // base ((it+2)&1 ? 0 : 65536) == ((it&1) ? 0 : 65536). The R5 code had
        // the ternary inverted, so every tile >= 2 read stale K/V.
        if (it + 2 < nkt) kvload(it + 2, (it & 1) ? 0u : 65536u);
    }

    // ---- epilogue ----
    float inv0 = 1.f / l0, inv1 = 1.f / l1;
    int grow = b * T_SEQ + r0;
    #pragma unroll
    for (int f = 0; f < 16; f++) {
        int col = h * HDIM + f * 8 + (lid & 3) * 2;
        *(float2*)&Out[(size_t)grow * 4096 + col] =
            make_float2(oacc[f][0] * inv0, oacc[f][1] * inv0);
        *(float2*)&Out[(size_t)(grow + 8) * 4096 + col] =
            make_float2(oacc[f][2] * inv1, oacc[f][3] * inv1);
    }
}

// ================= launcher =================
extern "C" void kernel_launch(void* const* d_in, const int* in_sizes, int n_in,
                              void* d_out, int out_size)
{
    const float* x  = (const float*)d_in[0];
    const float* wq = (const float*)d_in[1];
    const float* wk = (const float*)d_in[2];
    const float* wv = (const float*)d_in[3];
    const float* wo = (const float*)d_in[4];
    const int*   sp = (n_in > 5) ? (const int*)d_in[5] : nullptr;
    float* out = (float*)d_out;
    (void)in_sizes; (void)out_size;

    float *gq, *gk, *gv, *ga;
    cudaGetSymbolAddress((void**)&gq, g_q);
    cudaGetSymbolAddress((void**)&gk, g_k);
    cudaGetSymbolAddress((void**)&gv, g_v);
    cudaGetSymbolAddress((void**)&ga, g_attn);
    __nv_bfloat16 *xh, *xl, *ah, *al, *qh, *ql, *kh, *kl, *vh, *vl;
    __nv_bfloat16 *wqh, *wql, *wkh, *wkl, *wvh, *wvl, *woh, *wol;
    cudaGetSymbolAddress((void**)&xh, g_xh);   cudaGetSymbolAddress((void**)&xl, g_xl);
    cudaGetSymbolAddress((void**)&ah, g_ah);   cudaGetSymbolAddress((void**)&al, g_al);
    cudaGetSymbolAddress((void**)&qh, g_qh);   cudaGetSymbolAddress((void**)&ql, g_ql);
    cudaGetSymbolAddress((void**)&kh, g_kh);   cudaGetSymbolAddress((void**)&kl, g_kl);
    cudaGetSymbolAddress((void**)&vh, g_vh);   cudaGetSymbolAddress((void**)&vl, g_vl);
    cudaGetSymbolAddress((void**)&wqh, g_wqh); cudaGetSymbolAddress((void**)&wql, g_wql);
    cudaGetSymbolAddress((void**)&wkh, g_wkh); cudaGetSymbolAddress((void**)&wkl, g_wkl);
    cudaGetSymbolAddress((void**)&wvh, g_wvh); cudaGetSymbolAddress((void**)&wvl, g_wvl);
    cudaGetSymbolAddress((void**)&woh, g_woh); cudaGetSymbolAddress((void**)&wol, g_wol);

    cudaFuncSetAttribute(gemm3_kernel, cudaFuncAttributeMaxDynamicSharedMemorySize, GEMM_SMEM);
    cudaFuncSetAttribute(gemm3_big_kernel, cudaFuncAttributeMaxDynamicSharedMemorySize, BIG_SMEM);
    cudaFuncSetAttribute(attn_tc_kernel, cudaFuncAttributeMaxDynamicSharedMemorySize, ATT_SMEM);

    int n4x = BT * 4096 / 4;

    split_kernel<<<n4x / 256, 256>>>(x, xh, xl, n4x);
    tsplit_kernel<<<dim3(4096 / 32, 4096 / 32), 256>>>(wq, wqh, wql, 4096, 4096);
    gemm3_big_kernel<<<dim3(4096 / 256, BT / 128), 256, BIG_SMEM>>>(xh, xl, wqh, wql, gq, BT, 4096, 4096);
    tsplit_kernel<<<dim3(1024 / 32, 4096 / 32), 256>>>(wk, wkh, wkl, 4096, 1024);
    gemm3_kernel<<<dim3(1024 / 128, BT / 128), 256, GEMM_SMEM>>>(xh, xl, wkh, wkl, gk, BT, 1024, 4096);
    tsplit_kernel<<<dim3(1024 / 32, 4096 / 32), 256>>>(wv, wvh, wvl, 4096, 1024);
    gemm3_kernel<<<dim3(1024 / 128, BT / 128), 256, GEMM_SMEM>>>(xh, xl, wvh, wvl, gv, BT, 1024, 4096);
    tsplit_kernel<<<dim3(4096 / 32, 4096 / 32), 256>>>(wo, woh, wol, 4096, 4096);

    // RoPE + bf16 hi/lo split (scale baked into q)
    rope_split_kernel<<<(BT * 2048) / 256, 256>>>(gq, qh, ql, 4096, BT * 2048, sp,
                                                  0.08838834764831845f);
    rope_split_kernel<<<(BT * 512) / 256, 256>>>(gk, kh, kl, 1024, BT * 512, sp, 1.0f);
    split_kernel<<<(BT * 1024 / 4) / 256, 256>>>(gv, vh, vl, BT * 1024 / 4);

    // tensor-core flash attention
    attn_tc_kernel<<<dim3(T_SEQ / 128, NH, B_SZ), 256, ATT_SMEM>>>(qh, ql, kh, kl, vh, vl, ga);

    // output projection
    split_kernel<<<n4x / 256, 256>>>(ga, ah, al, n4x);
    gemm3_big_kernel<<<dim3(4096 / 256, BT / 128), 256, BIG_SMEM>>>(ah, al, woh, wol, out, BT, 4096, 4096);
}

// round 8
// speedup vs baseline: 3.6156x; 1.0111x over previous
#include <cuda_runtime.h>
#include <cuda_bf16.h>
#include <math.h>
#include <stdint.h>

#define B_SZ   2
#define T_SEQ  1024
#define BT     2048
#define NH     32
#define HDIM   128

// ================= scratch =================
__device__ float g_q[BT * 4096];
__device__ float g_kv[BT * 2048];
__device__ __nv_bfloat16 g_xh[BT * 4096], g_xl[BT * 4096];
__device__ __nv_bfloat16 g_ah[BT * 4096], g_al[BT * 4096];
__device__ __nv_bfloat16 g_qh[BT * 4096], g_ql[BT * 4096];
__device__ __nv_bfloat16 g_kh[BT * 1024], g_kl[BT * 1024];
__device__ __nv_bfloat16 g_vh[BT * 1024], g_vl[BT * 1024];
__device__ __nv_bfloat16 g_wqh[4096 * 4096], g_wql[4096 * 4096];
__device__ __nv_bfloat16 g_wkvh[2048 * 4096], g_wkvl[2048 * 4096];
__device__ __nv_bfloat16 g_woh[4096 * 4096], g_wol[4096 * 4096];

// ================= helpers =================
__device__ __forceinline__ uint32_t smem_u32(const void* p) {
    uint32_t a;
    asm("{ .reg .u64 t; cvta.to.shared.u64 t, %1; cvt.u32.u64 %0, t; }"
        : "=r"(a) : "l"(p));
    return a;
}
// GEMM tile swizzle: (rows)x32(k) bf16 tile
__device__ __forceinline__ uint32_t swz(uint32_t r, uint32_t u) {
    return ((r >> 1) << 7) | (((((r & 1) << 2) | u) ^ ((r >> 1) & 7)) << 4);
}
// attention tile swizzle: (rows)x128 bf16 tile, 16 16B-units/row
#define OFFA(r, u) (((uint32_t)(r)) * 256 + ((((uint32_t)(u)) ^ (((uint32_t)(r)) & 7)) << 4))

#define CP_ASYNC16(dst, src) \
    asm volatile("cp.async.cg.shared.global [%0], [%1], 16;" :: "r"(dst), "l"(src))
#define CP_COMMIT() asm volatile("cp.async.commit_group;" ::: "memory")
#define CP_WAIT0()  asm volatile("cp.async.wait_group 0;" ::: "memory")
#define CP_WAIT1()  asm volatile("cp.async.wait_group 1;" ::: "memory")
#define CP_WAIT2()  asm volatile("cp.async.wait_group 2;" ::: "memory")

#define LDSM4(r0, r1, r2, r3, a) \
    asm volatile("ldmatrix.sync.aligned.m8n8.x4.shared.b16 {%0,%1,%2,%3}, [%4];" \
        : "=r"(r0), "=r"(r1), "=r"(r2), "=r"(r3) : "r"(a))
#define LDSM4T(r0, r1, r2, r3, a) \
    asm volatile("ldmatrix.sync.aligned.m8n8.x4.trans.shared.b16 {%0,%1,%2,%3}, [%4];" \
        : "=r"(r0), "=r"(r1), "=r"(r2), "=r"(r3) : "r"(a))

#define MMA16816(c, a0, a1, a2, a3, b0, b1) \
    asm volatile("mma.sync.aligned.m16n8k16.row.col.f32.bf16.bf16.f32 " \
        "{%0,%1,%2,%3}, {%4,%5,%6,%7}, {%8,%9}, {%0,%1,%2,%3};" \
        : "+f"((c)[0]), "+f"((c)[1]), "+f"((c)[2]), "+f"((c)[3]) \
        : "r"(a0), "r"(a1), "r"(a2), "r"(a3), "r"(b0), "r"(b1))

__device__ __forceinline__ void pack_hl(float f0, float f1, uint32_t& h, uint32_t& l) {
    __nv_bfloat162 hh = __floats2bfloat162_rn(f0, f1);
    float r0 = f0 - __bfloat162float(hh.x);
    float r1 = f1 - __bfloat162float(hh.y);
    __nv_bfloat162 ll = __floats2bfloat162_rn(r0, r1);
    h = *(uint32_t*)&hh;
    l = *(uint32_t*)&ll;
}

// ============ split fp32 -> bf16 hi/lo (row-major dense) ============
__global__ void split_kernel(const float* __restrict__ in,
                             __nv_bfloat16* __restrict__ hi,
                             __nv_bfloat16* __restrict__ lo, int n4)
{
    int i = blockIdx.x * blockDim.x + threadIdx.x;
    if (i >= n4) return;
    float4 v = ((const float4*)in)[i];
    __nv_bfloat16 h0 = __float2bfloat16(v.x);
    __nv_bfloat16 h1 = __float2bfloat16(v.y);
    __nv_bfloat16 h2 = __float2bfloat16(v.z);
    __nv_bfloat16 h3 = __float2bfloat16(v.w);
    __nv_bfloat162* hp = (__nv_bfloat162*)hi;
    __nv_bfloat162* lp = (__nv_bfloat162*)lo;
    hp[2 * i]     = __nv_bfloat162(h0, h1);
    hp[2 * i + 1] = __nv_bfloat162(h2, h3);
    lp[2 * i]     = __nv_bfloat162(__float2bfloat16(v.x - __bfloat162float(h0)),
                                   __float2bfloat16(v.y - __bfloat162float(h1)));
    lp[2 * i + 1] = __nv_bfloat162(__float2bfloat16(v.z - __bfloat162float(h2)),
                                   __float2bfloat16(v.w - __bfloat162float(h3)));
}

// ============ strided split: in[row*in_stride4 + c4] (float4 units) ============
__global__ void splitstride_kernel(const float* __restrict__ in, int in_stride4,
                                   int cols4, __nv_bfloat16* __restrict__ hi,
                                   __nv_bfloat16* __restrict__ lo, int n4)
{
    int i = blockIdx.x * blockDim.x + threadIdx.x;
    if (i >= n4) return;
    int row = i / cols4;
    int c4 = i - row * cols4;
    float4 v = ((const float4*)in)[row * in_stride4 + c4];
    int o = row * cols4 + c4;
    __nv_bfloat16 h0 = __float2bfloat16(v.x);
    __nv_bfloat16 h1 = __float2bfloat16(v.y);
    __nv_bfloat16 h2 = __float2bfloat16(v.z);
    __nv_bfloat16 h3 = __float2bfloat16(v.w);
    __nv_bfloat162* hp = (__nv_bfloat162*)hi;
    __nv_bfloat162* lp = (__nv_bfloat162*)lo;
    hp[2 * o]     = __nv_bfloat162(h0, h1);
    hp[2 * o + 1] = __nv_bfloat162(h2, h3);
    lp[2 * o]     = __nv_bfloat162(__float2bfloat16(v.x - __bfloat162float(h0)),
                                   __float2bfloat16(v.y - __bfloat162float(h1)));
    lp[2 * o + 1] = __nv_bfloat162(__float2bfloat16(v.z - __bfloat162float(h2)),
                                   __float2bfloat16(v.w - __bfloat162float(h3)));
}

// ============ transpose + split v2: W[K][N] fp32 -> Wt[N][K] bf16 hi/lo ============
// 32(n) x 64(k) tile; coalesced 4B bf162 writes.
__global__ __launch_bounds__(256) void tsplit2_kernel(
    const float* __restrict__ W, __nv_bfloat16* __restrict__ hi,
    __nv_bfloat16* __restrict__ lo, int K, int N)
{
    __shared__ float s[32][66];    // [n][k], pad 2 keeps float2 8B-aligned
    const int n0 = blockIdx.x * 32, k0 = blockIdx.y * 64;
    const int tid = threadIdx.x;
    #pragma unroll
    for (int i = 0; i < 8; i++) {
        int idx = tid + i * 256;
        int r = idx >> 5;          // k-rel 0..63
        int c = idx & 31;          // n-rel
        s[c][r] = W[(size_t)(k0 + r) * N + n0 + c];
    }
    __syncthreads();
    #pragma unroll
    for (int i = 0; i < 4; i++) {
        int p = tid + i * 256;
        int row = p >> 5;          // n-rel 0..31
        int pr = p & 31;           // k-pair 0..31
        float2 v = *(float2*)&s[row][pr * 2];
        __nv_bfloat16 h0 = __float2bfloat16(v.x);
        __nv_bfloat16 h1 = __float2bfloat16(v.y);
        __nv_bfloat162 hh(h0, h1);
        __nv_bfloat162 ll(__float2bfloat16(v.x - __bfloat162float(h0)),
                          __float2bfloat16(v.y - __bfloat162float(h1)));
        size_t o = (size_t)(n0 + row) * K + k0 + pr * 2;
        *(uint32_t*)(hi + o) = *(uint32_t*)&hh;
        *(uint32_t*)(lo + o) = *(uint32_t*)&ll;
    }
}

// ============ RoPE + split (strided in/out) ============
__global__ void rope_split_kernel(const float* __restrict__ in, int in_stride,
                                  __nv_bfloat16* __restrict__ hi,
                                  __nv_bfloat16* __restrict__ lo, int out_stride,
                                  int total_pairs, const int* __restrict__ sp,
                                  float scale)
{
    int idx = blockIdx.x * blockDim.x + threadIdx.x;
    if (idx >= total_pairs) return;
    int halfout = out_stride >> 1;
    int row = idx / halfout;
    int p   = idx - row * halfout;
    int c0  = p * 2;
    int j0  = c0 & (HDIM - 1);
    int start = (sp == nullptr) ? 0 : *sp;
    float t = (float)(start + (row & (T_SEQ - 1)));
    const float lf = 9.210340371976184f;
    float a0 = t * expf(-(float)(j0 & 63)       * (lf / 64.f));
    float a1 = t * expf(-(float)((j0 + 1) & 63) * (lf / 64.f));
    float c0v, s0v, c1v, s1v;
    sincosf(a0, &s0v, &c0v);
    sincosf(a1, &s1v, &c1v);
    const float* base = in + (size_t)row * in_stride + c0;
    float x0 = base[0], x1 = base[1];
    float y0 = (x0 * c0v - x1 * s0v) * scale;
    float y1 = (x1 * c1v + x0 * s1v) * scale;
    uint32_t h, l;
    pack_hl(y0, y1, h, l);
    *(uint32_t*)(hi + (size_t)row * out_stride + c0) = h;
    *(uint32_t*)(lo + (size_t)row * out_stride + c0) = l;
}

// ============ bf16x3 GEMM 128x128: C = A @ Bt^T ============
#define KC      32
#define NSTAGE  3
#define TILE_B  8192
#define STAGE_B (4 * TILE_B)
#define GEMM_SMEM (NSTAGE * STAGE_B)

__global__ __launch_bounds__(256, 1) void gemm3_kernel(
    const __nv_bfloat16* __restrict__ Ah, const __nv_bfloat16* __restrict__ Al,
    const __nv_bfloat16* __restrict__ Bh, const __nv_bfloat16* __restrict__ Bl,
    float* __restrict__ C, int M, int N, int K)
{
    extern __shared__ char smem[];
    const uint32_t sb = smem_u32(smem);
    const int tid = threadIdx.x, wid = tid >> 5, lid = tid & 31;
    const int m0 = blockIdx.y * 128, n0 = blockIdx.x * 128;
    const int warp_m = wid & 1, warp_n = wid >> 1;
    const int NCH = K / KC;

    uint32_t rel_a[4][2], rel_b[2][2];
    {
        uint32_t ar = (uint32_t)(warp_m * 64 + (lid & 15));
        uint32_t au = (uint32_t)(lid >> 4);
        #pragma unroll
        for (int mi = 0; mi < 4; mi++)
            #pragma unroll
            for (int k16 = 0; k16 < 2; k16++)
                rel_a[mi][k16] = swz(ar + mi * 16, au + k16 * 2);
        uint32_t br = (uint32_t)(warp_n * 32 + (lid & 7) + ((lid >> 4) << 3));
        uint32_t bu = (uint32_t)((lid >> 3) & 1);
        #pragma unroll
        for (int ng = 0; ng < 2; ng++)
            #pragma unroll
            for (int k16 = 0; k16 < 2; k16++)
                rel_b[ng][k16] = swz(br + ng * 16, bu + k16 * 2);
    }

    float acc[4][4][4];
    #pragma unroll
    for (int mi = 0; mi < 4; mi++)
        #pragma unroll
        for (int ni = 0; ni < 4; ni++)
            #pragma unroll
            for (int j = 0; j < 4; j++) acc[mi][ni][j] = 0.f;

    auto load_stage = [&](int s, int chunk) {
        const int k0 = chunk * KC;
        const uint32_t st = sb + s * STAGE_B;
        #pragma unroll
        for (int t = 0; t < 8; t++) {
            int g = t * 256 + tid;
            int tile = g >> 9;
            int w = g & 511;
            int r = w >> 2, u = w & 3;
            uint32_t dst = st + tile * TILE_B + swz(r, u);
            const __nv_bfloat16* src;
            if (tile == 0)      src = Ah + (size_t)(m0 + r) * K + k0 + u * 8;
            else if (tile == 1) src = Al + (size_t)(m0 + r) * K + k0 + u * 8;
            else if (tile == 2) src = Bh + (size_t)(n0 + r) * K + k0 + u * 8;
            else                src = Bl + (size_t)(n0 + r) * K + k0 + u * 8;
            CP_ASYNC16(dst, src);
        }
    };

    load_stage(0, 0); CP_COMMIT();
    load_stage(1, 1); CP_COMMIT();

    for (int i = 0; i < NCH; i++) {
        CP_WAIT1();
        __syncthreads();
        int nxt = i + NSTAGE - 1;
        if (nxt < NCH) load_stage(nxt % NSTAGE, nxt);
        CP_COMMIT();

        const uint32_t st = sb + (i % NSTAGE) * STAGE_B;
        const uint32_t ah_b = st, al_b = st + TILE_B;
        const uint32_t bh_b = st + 2 * TILE_B, bl_b = st + 3 * TILE_B;

        #pragma unroll
        for (int k16 = 0; k16 < 2; k16++) {
            uint32_t afh[4][4], afl[4][4], bfh[2][4], bfl[2][4];
            #pragma unroll
            for (int mi = 0; mi < 4; mi++) {
                LDSM4(afh[mi][0], afh[mi][1], afh[mi][2], afh[mi][3], ah_b + rel_a[mi][k16]);
                LDSM4(afl[mi][0], afl[mi][1], afl[mi][2], afl[mi][3], al_b + rel_a[mi][k16]);
            }
            #pragma unroll
            for (int ng = 0; ng < 2; ng++) {
                LDSM4(bfh[ng][0], bfh[ng][1], bfh[ng][2], bfh[ng][3], bh_b + rel_b[ng][k16]);
                LDSM4(bfl[ng][0], bfl[ng][1], bfl[ng][2], bfl[ng][3], bl_b + rel_b[ng][k16]);
            }
            #pragma unroll
            for (int mi = 0; mi < 4; mi++)
                #pragma unroll
                for (int ni = 0; ni < 4; ni++) {
                    int ng = ni >> 1, rp = (ni & 1) * 2;
                    MMA16816(acc[mi][ni], afh[mi][0], afh[mi][1], afh[mi][2], afh[mi][3],
                             bfh[ng][rp], bfh[ng][rp + 1]);
                    MMA16816(acc[mi][ni], afh[mi][0], afh[mi][1], afh[mi][2], afh[mi][3],
                             bfl[ng][rp], bfl[ng][rp + 1]);
                    MMA16816(acc[mi][ni], afl[mi][0], afl[mi][1], afl[mi][2], afl[mi][3],
                             bfh[ng][rp], bfh[ng][rp + 1]);
                }
        }
    }

    #pragma unroll
    for (int mi = 0; mi < 4; mi++) {
        int row = m0 + warp_m * 64 + mi * 16 + (lid >> 2);
        #pragma unroll
        for (int ni = 0; ni < 4; ni++) {
            int col = n0 + warp_n * 32 + ni * 8 + (lid & 3) * 2;
            *(float2*)&C[(size_t)row * N + col] = make_float2(acc[mi][ni][0], acc[mi][ni][1]);
            *(float2*)&C[(size_t)(row + 8) * N + col] = make_float2(acc[mi][ni][2], acc[mi][ni][3]);
        }
    }
}

// ============ bf16x3 GEMM 128x256 (for Q/O) ============
#define NSTB    4
#define A_TB    8192
#define B_TB    16384
#define STAGE_BB (2 * A_TB + 2 * B_TB)
#define BIG_SMEM (NSTB * STAGE_BB)

__global__ __launch_bounds__(256, 1) void gemm3_big_kernel(
    const __nv_bfloat16* __restrict__ Ah, const __nv_bfloat16* __restrict__ Al,
    const __nv_bfloat16* __restrict__ Bh, const __nv_bfloat16* __restrict__ Bl,
    float* __restrict__ C, int M, int N, int K)
{
    extern __shared__ char smem[];
    const uint32_t sb = smem_u32(smem);
    const int tid = threadIdx.x, wid = tid >> 5, lid = tid & 31;
    const int m0 = blockIdx.y * 128, n0 = blockIdx.x * 256;
    const int warp_m = wid & 1, warp_n = wid >> 1;
    const int NCH = K / KC;

    uint32_t rel_a[4][2], rel_b[4][2];
    {
        uint32_t ar = (uint32_t)(warp_m * 64 + (lid & 15));
        uint32_t au = (uint32_t)(lid >> 4);
        #pragma unroll
        for (int mi = 0; mi < 4; mi++)
            #pragma unroll
            for (int k16 = 0; k16 < 2; k16++)
                rel_a[mi][k16] = swz(ar + mi * 16, au + k16 * 2);
        uint32_t br = (uint32_t)(warp_n * 64 + (lid & 7) + ((lid >> 4) << 3));
        uint32_t bu = (uint32_t)((lid >> 3) & 1);
        #pragma unroll
        for (int ng = 0; ng < 4; ng++)
            #pragma unroll
            for (int k16 = 0; k16 < 2; k16++)
                rel_b[ng][k16] = swz(br + ng * 16, bu + k16 * 2);
    }

    float acc[4][8][4];
    #pragma unroll
    for (int mi = 0; mi < 4; mi++)
        #pragma unroll
        for (int ni = 0; ni < 8; ni++)
            #pragma unroll
            for (int j = 0; j < 4; j++) acc[mi][ni][j] = 0.f;

    auto load_stage = [&](int s, int chunk) {
        const int k0 = chunk * KC;
        const uint32_t st = sb + s * STAGE_BB;
        #pragma unroll
        for (int t = 0; t < 12; t++) {
            int g = t * 256 + tid;
            uint32_t dst;
            const __nv_bfloat16* src;
            if (g < 1024) {
                int r = (g & 511) >> 2, u = g & 3;
                dst = st + (g >> 9) * A_TB + swz(r, u);
                src = ((g >> 9) ? Al : Ah) + (size_t)(m0 + r) * K + k0 + u * 8;
            } else {
                int w = g - 1024;
                int r = (w & 1023) >> 2, u = w & 3;
                dst = st + 2 * A_TB + (w >> 10) * B_TB + swz(r, u);
                src = ((w >> 10) ? Bl : Bh) + (size_t)(n0 + r) * K + k0 + u * 8;
            }
            CP_ASYNC16(dst, src);
        }
    };

    load_stage(0, 0); CP_COMMIT();
    load_stage(1, 1); CP_COMMIT();
    load_stage(2, 2); CP_COMMIT();

    for (int i = 0; i < NCH; i++) {
        CP_WAIT2();
        __syncthreads();
        int nxt = i + NSTB - 1;
        if (nxt < NCH) load_stage(nxt % NSTB, nxt);
        CP_COMMIT();

        const uint32_t st = sb + (i % NSTB) * STAGE_BB;
        const uint32_t ah_b = st, al_b = st + A_TB;
        const uint32_t bh_b = st + 2 * A_TB, bl_b = st + 2 * A_TB + B_TB;

        #pragma unroll
        for (int k16 = 0; k16 < 2; k16++) {
            uint32_t afh[4][4], afl[4][4];
            #pragma unroll
            for (int mi = 0; mi < 4; mi++) {
                LDSM4(afh[mi][0], afh[mi][1], afh[mi][2], afh[mi][3], ah_b + rel_a[mi][k16]);
                LDSM4(afl[mi][0], afl[mi][1], afl[mi][2], afl[mi][3], al_b + rel_a[mi][k16]);
            }
            #pragma unroll
            for (int ng = 0; ng < 4; ng++) {
                uint32_t bfh[4], bfl[4];
                LDSM4(bfh[0], bfh[1], bfh[2], bfh[3], bh_b + rel_b[ng][k16]);
                LDSM4(bfl[0], bfl[1], bfl[2], bfl[3], bl_b + rel_b[ng][k16]);
                #pragma unroll
                for (int mi = 0; mi < 4; mi++)
                    #pragma unroll
                    for (int rp = 0; rp < 2; rp++) {
                        float* a = acc[mi][ng * 2 + rp];
                        MMA16816(a, afh[mi][0], afh[mi][1], afh[mi][2], afh[mi][3],
                                 bfh[rp * 2], bfh[rp * 2 + 1]);
                        MMA16816(a, afh[mi][0], afh[mi][1], afh[mi][2], afh[mi][3],
                                 bfl[rp * 2], bfl[rp * 2 + 1]);
                        MMA16816(a, afl[mi][0], afl[mi][1], afl[mi][2], afl[mi][3],
                                 bfh[rp * 2], bfh[rp * 2 + 1]);
                    }
            }
        }
    }

    #pragma unroll
    for (int mi = 0; mi < 4; mi++) {
        int row = m0 + warp_m * 64 + mi * 16 + (lid >> 2);
        #pragma unroll
        for (int ni = 0; ni < 8; ni++) {
            int col = n0 + warp_n * 64 + ni * 8 + (lid & 3) * 2;
            *(float2*)&C[(size_t)row * N + col] = make_float2(acc[mi][ni][0], acc[mi][ni][1]);
            *(float2*)&C[(size_t)(row + 8) * N + col] = make_float2(acc[mi][ni][2], acc[mi][ni][3]);
        }
    }
}

// ============ Tensor-core flash attention (causal, GQA, bf16x3) ============
// Writes bf16 hi/lo output directly (fused split for the O-projection).
#define ATT_SMEM 131072

__global__ __launch_bounds__(256, 1) void attn_tc_kernel(
    const __nv_bfloat16* __restrict__ Qh, const __nv_bfloat16* __restrict__ Ql,
    const __nv_bfloat16* __restrict__ Kh, const __nv_bfloat16* __restrict__ Kl,
    const __nv_bfloat16* __restrict__ Vh, const __nv_bfloat16* __restrict__ Vl,
    __nv_bfloat16* __restrict__ OutH, __nv_bfloat16* __restrict__ OutL)
{
    extern __shared__ char smem[];
    const uint32_t sb = smem_u32(smem);
    const int tid = threadIdx.x, wid = tid >> 5, lid = tid & 31;
    const int b = blockIdx.z, h = blockIdx.y, m0 = blockIdx.x * 128;
    const int kvh = h >> 2;

    // --- Q load into region A (hi @0, lo @32K) ---
    #pragma unroll
    for (int i = 0; i < 16; i++) {
        int idx = i * 256 + tid;
        int t = idx >> 11, w = idx & 2047;
        int r = w >> 4, u = w & 15;
        const __nv_bfloat16* src = (t ? Ql : Qh)
            + (size_t)(b * T_SEQ + m0 + r) * 4096 + h * HDIM + u * 8;
        CP_ASYNC16(sb + t * 32768 + OFFA(r, u), src);
    }
    CP_COMMIT();

    auto kvload = [&](int kt, uint32_t base) {
        #pragma unroll
        for (int i = 0; i < 16; i++) {
            int idx = i * 256 + tid;
            int t = idx >> 10, w = idx & 1023;
            int r = w >> 4, u = w & 15;
            const __nv_bfloat16* arr = (t == 0) ? Kh : (t == 1) ? Kl : (t == 2) ? Vh : Vl;
            const __nv_bfloat16* src = arr
                + (size_t)(b * T_SEQ + kt * 64 + r) * 1024 + kvh * HDIM + u * 8;
            CP_ASYNC16(sb + base + t * 16384 + OFFA(r, u), src);
        }
        CP_COMMIT();
    };

    const int nkt = (m0 + 128) / 64;
    kvload(0, 65536);

    CP_WAIT1();
    __syncthreads();

    uint32_t qfh[8][4], qfl[8][4];
    {
        uint32_t r = (uint32_t)(wid * 16 + (lid & 15));
        uint32_t ub = (uint32_t)(lid >> 4);
        #pragma unroll
        for (int ks = 0; ks < 8; ks++) {
            uint32_t off = OFFA(r, ks * 2 + ub);
            LDSM4(qfh[ks][0], qfh[ks][1], qfh[ks][2], qfh[ks][3], sb + off);
            LDSM4(qfl[ks][0], qfl[ks][1], qfl[ks][2], qfl[ks][3], sb + 32768 + off);
        }
    }
    __syncthreads();
    if (nkt > 1) kvload(1, 0);

    float oacc[16][4];
    #pragma unroll
    for (int f = 0; f < 16; f++)
        #pragma unroll
        for (int j = 0; j < 4; j++) oacc[f][j] = 0.f;
    float mr0 = -INFINITY, mr1 = -INFINITY, l0 = 0.f, l1 = 0.f;

    const int row_lo = m0 + wid * 16;
    const int r0 = row_lo + (lid >> 2);

    for (int it = 0; it < nkt; it++) {
        if (it + 1 < nkt) { CP_WAIT1(); } else { CP_WAIT0(); }
        __syncthreads();
        const uint32_t stg = sb + ((it & 1) ? 0u : 65536u);
        const int ktb = it * 64;

        if (ktb <= row_lo + 15) {
            float s[8][4];
            #pragma unroll
            for (int j = 0; j < 8; j++)
                #pragma unroll
                for (int q = 0; q < 4; q++) s[j][q] = 0.f;

            uint32_t br = (uint32_t)((lid & 7) + ((lid >> 4) << 3));
            uint32_t bu = (uint32_t)((lid >> 3) & 1);
            #pragma unroll
            for (int ks = 0; ks < 8; ks++) {
                #pragma unroll
                for (int jj = 0; jj < 4; jj++) {
                    uint32_t kh0, kh1, kh2, kh3, kl0, kl1, kl2, kl3;
                    uint32_t off = OFFA(jj * 16 + br, ks * 2 + bu);
                    LDSM4(kh0, kh1, kh2, kh3, stg + off);
                    LDSM4(kl0, kl1, kl2, kl3, stg + 16384 + off);
                    MMA16816(s[jj * 2],     qfh[ks][0], qfh[ks][1], qfh[ks][2], qfh[ks][3], kh0, kh1);
                    MMA16816(s[jj * 2 + 1], qfh[ks][0], qfh[ks][1], qfh[ks][2], qfh[ks][3], kh2, kh3);
                    MMA16816(s[jj * 2],     qfh[ks][0], qfh[ks][1], qfh[ks][2], qfh[ks][3], kl0, kl1);
                    MMA16816(s[jj * 2 + 1], qfh[ks][0], qfh[ks][1], qfh[ks][2], qfh[ks][3], kl2, kl3);
                    MMA16816(s[jj * 2],     qfl[ks][0], qfl[ks][1], qfl[ks][2], qfl[ks][3], kh0, kh1);
                    MMA16816(s[jj * 2 + 1], qfl[ks][0], qfl[ks][1], qfl[ks][2], qfl[ks][3], kh2, kh3);
                }
            }

            if (ktb + 63 > row_lo) {
                #pragma unroll
                for (int j = 0; j < 8; j++) {
                    int c = ktb + j * 8 + (lid & 3) * 2;
                    if (c > r0)         s[j][0] = -INFINITY;
                    if (c + 1 > r0)     s[j][1] = -INFINITY;
                    if (c > r0 + 8)     s[j][2] = -INFINITY;
                    if (c + 1 > r0 + 8) s[j][3] = -INFINITY;
                }
            }

            float mx0 = -INFINITY, mx1 = -INFINITY;
            #pragma unroll
            for (int j = 0; j < 8; j++) {
                mx0 = fmaxf(mx0, fmaxf(s[j][0], s[j][1]));
                mx1 = fmaxf(mx1, fmaxf(s[j][2], s[j][3]));
            }
            mx0 = fmaxf(mx0, __shfl_xor_sync(0xFFFFFFFFu, mx0, 1));
            mx0 = fmaxf(mx0, __shfl_xor_sync(0xFFFFFFFFu, mx0, 2));
            mx1 = fmaxf(mx1, __shfl_xor_sync(0xFFFFFFFFu, mx1, 1));
            mx1 = fmaxf(mx1, __shfl_xor_sync(0xFFFFFFFFu, mx1, 2));
            float mn0 = fmaxf(mr0, mx0), mn1 = fmaxf(mr1, mx1);
            float c0 = __expf(mr0 - mn0), c1 = __expf(mr1 - mn1);
            mr0 = mn0; mr1 = mn1;
            float rs0 = 0.f, rs1 = 0.f;
            #pragma unroll
            for (int j = 0; j < 8; j++) {
                s[j][0] = __expf(s[j][0] - mn0);
                s[j][1] = __expf(s[j][1] - mn0);
                s[j][2] = __expf(s[j][2] - mn1);
                s[j][3] = __expf(s[j][3] - mn1);
                rs0 += s[j][0] + s[j][1];
                rs1 += s[j][2] + s[j][3];
            }
            rs0 += __shfl_xor_sync(0xFFFFFFFFu, rs0, 1);
            rs0 += __shfl_xor_sync(0xFFFFFFFFu, rs0, 2);
            rs1 += __shfl_xor_sync(0xFFFFFFFFu, rs1, 1);
            rs1 += __shfl_xor_sync(0xFFFFFFFFu, rs1, 2);
            l0 = l0 * c0 + rs0;
            l1 = l1 * c1 + rs1;
            #pragma unroll
            for (int f = 0; f < 16; f++) {
                oacc[f][0] *= c0; oacc[f][1] *= c0;
                oacc[f][2] *= c1; oacc[f][3] *= c1;
            }

            #pragma unroll
            for (int ks2 = 0; ks2 < 4; ks2++) {
                int j0 = ks2 * 2, j1 = j0 + 1;
                uint32_t pah[4], pal[4];
                pack_hl(s[j0][0], s[j0][1], pah[0], pal[0]);
                pack_hl(s[j0][2], s[j0][3], pah[1], pal[1]);
                pack_hl(s[j1][0], s[j1][1], pah[2], pal[2]);
                pack_hl(s[j1][2], s[j1][3], pah[3], pal[3]);
                uint32_t vr = (uint32_t)(ks2 * 16 + (lid & 15));
                uint32_t vub = (uint32_t)(lid >> 4);
                #pragma unroll
                for (int ng = 0; ng < 8; ng++) {
                    uint32_t vh0, vh1, vh2, vh3, vl0, vl1, vl2, vl3;
                    uint32_t off = OFFA(vr, ng * 2 + vub);
                    LDSM4T(vh0, vh1, vh2, vh3, stg + 32768 + off);
                    LDSM4T(vl0, vl1, vl2, vl3, stg + 49152 + off);
                    MMA16816(oacc[ng * 2],     pah[0], pah[1], pah[2], pah[3], vh0, vh1);
                    MMA16816(oacc[ng * 2 + 1], pah[0], pah[1], pah[2], pah[3], vh2, vh3);
                    MMA16816(oacc[ng * 2],     pah[0], pah[1], pah[2], pah[3], vl0, vl1);
                    MMA16816(oacc[ng * 2 + 1], pah[0], pah[1], pah[2], pah[3], vl2, vl3);
                    MMA16816(oacc[ng * 2],     pal[0], pal[1], pal[2], pal[3], vh0, vh1);
                    MMA16816(oacc[ng * 2 + 1], pal[0], pal[1], pal[2], pal[3], vh2, vh3);
                }
            }
        }
        __syncthreads();
        if (it + 2 < nkt) kvload(it + 2, (it & 1) ? 0u : 65536u);
    }

    // ---- epilogue: normalized bf16 hi/lo directly ----
    float inv0 = 1.f / l0, inv1 = 1.f / l1;
    size_t grow = (size_t)(b * T_SEQ + r0);
    #pragma unroll
    for (int f = 0; f < 16; f++) {
        int col = h * HDIM + f * 8 + (lid & 3) * 2;
        uint32_t hh, ll;
        pack_hl(oacc[f][0] * inv0, oacc[f][1] * inv0, hh, ll);
        *(uint32_t*)(OutH + grow * 4096 + col) = hh;
        *(uint32_t*)(OutL + grow * 4096 + col) = ll;
        pack_hl(oacc[f][2] * inv1, oacc[f][3] * inv1, hh, ll);
        *(uint32_t*)(OutH + (grow + 8) * 4096 + col) = hh;
        *(uint32_t*)(OutL + (grow + 8) * 4096 + col) = ll;
    }
}

// ================= launcher =================
extern "C" void kernel_launch(void* const* d_in, const int* in_sizes, int n_in,
                              void* d_out, int out_size)
{
    const float* x  = (const float*)d_in[0];
    const float* wq = (const float*)d_in[1];
    const float* wk = (const float*)d_in[2];
    const float* wv = (const float*)d_in[3];
    const float* wo = (const float*)d_in[4];
    const int*   sp = (n_in > 5) ? (const int*)d_in[5] : nullptr;
    float* out = (float*)d_out;
    (void)in_sizes; (void)out_size;

    float *gq, *gkv;
    cudaGetSymbolAddress((void**)&gq, g_q);
    cudaGetSymbolAddress((void**)&gkv, g_kv);
    __nv_bfloat16 *xh, *xl, *ah, *al, *qh, *ql, *kh, *kl, *vh, *vl;
    __nv_bfloat16 *wqh, *wql, *wkvh, *wkvl, *woh, *wol;
    cudaGetSymbolAddress((void**)&xh, g_xh);     cudaGetSymbolAddress((void**)&xl, g_xl);
    cudaGetSymbolAddress((void**)&ah, g_ah);     cudaGetSymbolAddress((void**)&al, g_al);
    cudaGetSymbolAddress((void**)&qh, g_qh);     cudaGetSymbolAddress((void**)&ql, g_ql);
    cudaGetSymbolAddress((void**)&kh, g_kh);     cudaGetSymbolAddress((void**)&kl, g_kl);
    cudaGetSymbolAddress((void**)&vh, g_vh);     cudaGetSymbolAddress((void**)&vl, g_vl);
    cudaGetSymbolAddress((void**)&wqh, g_wqh);   cudaGetSymbolAddress((void**)&wql, g_wql);
    cudaGetSymbolAddress((void**)&wkvh, g_wkvh); cudaGetSymbolAddress((void**)&wkvl, g_wkvl);
    cudaGetSymbolAddress((void**)&woh, g_woh);   cudaGetSymbolAddress((void**)&wol, g_wol);

    cudaFuncSetAttribute(gemm3_kernel, cudaFuncAttributeMaxDynamicSharedMemorySize, GEMM_SMEM);
    cudaFuncSetAttribute(gemm3_big_kernel, cudaFuncAttributeMaxDynamicSharedMemorySize, BIG_SMEM);
    cudaFuncSetAttribute(attn_tc_kernel, cudaFuncAttributeMaxDynamicSharedMemorySize, ATT_SMEM);

    int n4x = BT * 4096 / 4;

    // launches 0..4: splits (ncu -s 5 captures launch 5 = big Q GEMM)
    split_kernel<<<n4x / 256, 256>>>(x, xh, xl, n4x);                       // 0
    tsplit2_kernel<<<dim3(4096 / 32, 4096 / 64), 256>>>(wq, wqh, wql, 4096, 4096);   // 1
    tsplit2_kernel<<<dim3(1024 / 32, 4096 / 64), 256>>>(wk, wkvh, wkvl, 4096, 1024); // 2
    tsplit2_kernel<<<dim3(1024 / 32, 4096 / 64), 256>>>(wv, wkvh + (size_t)1024 * 4096,
                                                        wkvl + (size_t)1024 * 4096, 4096, 1024); // 3
    tsplit2_kernel<<<dim3(4096 / 32, 4096 / 64), 256>>>(wo, woh, wol, 4096, 4096);   // 4

    // 5: big Q projection (PROFILED)
    gemm3_big_kernel<<<dim3(4096 / 256, BT / 128), 256, BIG_SMEM>>>(xh, xl, wqh, wql, gq, BT, 4096, 4096);
    // 6: merged K|V projection (N = 2048)
    gemm3_kernel<<<dim3(2048 / 128, BT / 128), 256, GEMM_SMEM>>>(xh, xl, wkvh, wkvl, gkv, BT, 2048, 4096);

    // RoPE + bf16 hi/lo split (scale baked into q)
    rope_split_kernel<<<(BT * 2048) / 256, 256>>>(gq, 4096, qh, ql, 4096,
                                                  BT * 2048, sp, 0.08838834764831845f);
    rope_split_kernel<<<(BT * 512) / 256, 256>>>(gkv, 2048, kh, kl, 1024,
                                                 BT * 512, sp, 1.0f);
    splitstride_kernel<<<(BT * 256) / 256, 256>>>(gkv + 1024, 512, 256, vh, vl, BT * 256);

    // tensor-core flash attention (emits bf16 hi/lo directly)
    attn_tc_kernel<<<dim3(T_SEQ / 128, NH, B_SZ), 256, ATT_SMEM>>>(qh, ql, kh, kl, vh, vl, ah, al);

    // output projection
    gemm3_big_kernel<<<dim3(4096 / 256, BT / 128), 256, BIG_SMEM>>>(ah, al, woh, wol, out, BT, 4096, 4096);
}